// round 14
// baseline (speedup 1.0000x reference)
#include <cuda_runtime.h>
#include <cuda_bf16.h>
#include <math.h>
#include <stdint.h>

#define BB    4
#define TPP   4
#define TFF   2
#define NPAIR (BB*TFF)
#define RAD   4
#define NS    81
#define NFR   (BB*TPP)

// ---------------- scratch ---------------------------------------------------------
__device__ int   g_idx[NPAIR];
__device__ int   g_needed[NFR];
__device__ float g_pf0[(size_t)NFR * 128 * 6400];
__device__ float g_pf1[(size_t)NFR * 256 * 1600];
__device__ float g_pf2[(size_t)NFR * 512 * 400];
__device__ __nv_bfloat16 g_w0a[128*128],  g_w0b[128*128];
__device__ __nv_bfloat16 g_w1a[256*256],  g_w1b[256*256];
__device__ __nv_bfloat16 g_w2a[512*512],  g_w2b[512*512];

// ---------------- prep ------------------------------------------------------------
__global__ void prep_kernel(const int* __restrict__ pci, const int* __restrict__ fci)
{
    if (threadIdx.x != 0 || blockIdx.x != 0) return;
    for (int n = 0; n < NFR; n++) g_needed[n] = 0;
    for (int i = 0; i < BB; i++) {
        int p_pos = TPP - 2;
        for (int j = 0; j < TFF; j++) {
            int f_i = fci[i * TFF + j];
            while (p_pos >= 0) {
                if (p_pos == 0 || f_i < -pci[i * TPP + p_pos - 1]) {
                    int id = p_pos + i * TPP;
                    g_idx[i * TFF + j] = id;
                    g_needed[id] = 1;
                    break;
                }
                p_pos--;
            }
        }
        g_needed[i * TPP + (TPP - 1)] = 1;
    }
}

// ---------------- W split ----------------------------------------------------------
union BV8 { __nv_bfloat16 h[8]; uint4 u; };

__device__ __forceinline__ void split8(const float* v, uint4* ua, uint4* ub)
{
    BV8 a, b;
#pragma unroll
    for (int j = 0; j < 8; j++) {
        __nv_bfloat16 h = __float2bfloat16(v[j]);
        a.h[j] = h;
        b.h[j] = __float2bfloat16(v[j] - __bfloat162float(h));
    }
    *ua = a.u; *ub = b.u;
}

struct SplitW {
    const float* w[3];
    __nv_bfloat16 *wa[3], *wb[3];
};

__global__ void wsplit_all(SplitW S)
{
    int lvl = blockIdx.y;
    int nE  = (128 << lvl) * (128 << lvl);
    int i   = (blockIdx.x * 256 + threadIdx.x) * 8;
    if (i < nE) {
        float v[8];
        *(float4*)&v[0] = *(const float4*)(S.w[lvl] + i);
        *(float4*)&v[4] = *(const float4*)(S.w[lvl] + i + 4);
        split8(v, (uint4*)(S.wa[lvl] + i), (uint4*)(S.wb[lvl] + i));
    }
}

// ---------------- mma.sync bf16 helpers -------------------------------------------
__device__ __forceinline__ uint32_t smem_u32(const void* p)
{
    uint32_t a;
    asm("{ .reg .u64 t; cvta.to.shared.u64 t, %1; cvt.u32.u64 %0, t; }" : "=r"(a) : "l"(p));
    return a;
}

__device__ __forceinline__ void ldm_x4(uint32_t* r, uint32_t addr)
{
    asm volatile("ldmatrix.sync.aligned.m8n8.x4.shared.b16 {%0,%1,%2,%3}, [%4];"
                 : "=r"(r[0]), "=r"(r[1]), "=r"(r[2]), "=r"(r[3]) : "r"(addr));
}

__device__ __forceinline__ void ldm_x4t(uint32_t* r, uint32_t addr)
{
    asm volatile("ldmatrix.sync.aligned.m8n8.x4.trans.shared.b16 {%0,%1,%2,%3}, [%4];"
                 : "=r"(r[0]), "=r"(r[1]), "=r"(r[2]), "=r"(r[3]) : "r"(addr));
}

__device__ __forceinline__ void mma16(float* c, const uint32_t* a, const uint32_t* b)
{
    asm volatile(
        "mma.sync.aligned.m16n8k16.row.col.f32.bf16.bf16.f32 "
        "{%0,%1,%2,%3}, {%4,%5,%6,%7}, {%8,%9}, {%0,%1,%2,%3};"
        : "+f"(c[0]), "+f"(c[1]), "+f"(c[2]), "+f"(c[3])
        : "r"(a[0]), "r"(a[1]), "r"(a[2]), "r"(a[3]), "r"(b[0]), "r"(b[1]));
}

__device__ __forceinline__ void cpa16(uint32_t dst, const void* src)
{
    asm volatile("cp.async.cg.shared.global [%0], [%1], 16;" :: "r"(dst), "l"(src));
}

__device__ __forceinline__ float silu(float y) { return y / (1.0f + expf(-y)); }

// ---------------- conv (R12, banked) ----------------------------------------------
#define BUFSZ 49152

struct ConvTC {
    const __nv_bfloat16 *wa[3], *wb[3];
    const float *x[3];
    const float *gg[3], *bb[3], *mm[3], *vv[3];
    float *pf[3];
};

__global__ void __launch_bounds__(256, 2) conv_bf16_kernel(ConvTC P)
{
    int n = blockIdx.z;
    if (!g_needed[n]) return;

    int bx = blockIdx.x, lvl, p0, d0;
    if (bx < 50)      { lvl = 0; p0 = bx * 128; d0 = 0; }
    else if (bx < 76) { int r = bx - 50; lvl = 1; p0 = (r % 13) * 128; d0 = (r / 13) * 128; }
    else              { int r = bx - 76; lvl = 2; p0 = (r & 3) * 128;  d0 = (r >> 2) * 128; }
    const int C  = 128 << lvl;
    const int HW = 6400 >> (2 * lvl);
    const int NC = C >> 5;

    extern __shared__ uint32_t dsm[];
    char* smp = (char*)dsm;
    const int tid  = threadIdx.x;
    const int lane = tid & 31;
    const int wid  = tid >> 5;
    const int m_off = (wid & 1) * 64;
    const int n_off = (wid >> 1) * 32;
    const int g  = lane >> 2;
    const int tg = lane & 3;
    const uint32_t smb = smem_u32(dsm);

    const __nv_bfloat16* wA1 = P.wa[lvl] + (size_t)d0 * C;
    const __nv_bfloat16* wA2 = P.wb[lvl] + (size_t)d0 * C;
    const float*         xf  = P.x[lvl] + (size_t)n * C * HW;

    float acc[4][4][4];
#pragma unroll
    for (int mi = 0; mi < 4; mi++)
#pragma unroll
        for (int ni = 0; ni < 4; ni++)
#pragma unroll
            for (int r = 0; r < 4; r++) acc[mi][ni][r] = 0.f;

    const int ar0 = tid >> 2,          acb0 = tid & 3;
    const int ar1 = (tid + 256) >> 2,  acb1 = (tid + 256) & 3;
    const uint32_t adof0 = ar0 * 64 + ((acb0 ^ ((ar0 >> 1) & 3)) << 4);
    const uint32_t adof1 = ar1 * 64 + ((acb1 ^ ((ar1 >> 1) & 3)) << 4);

    const int r2  = tid >> 3;
    const int cg  = (tid & 7) * 16;
    const int nb0 = (tid & 7) * 2;
    const uint32_t bo0 = r2 * 256 + ((nb0 ^ (r2 & 7)) << 4);
    const uint32_t bo1 = r2 * 256 + (((nb0 + 1) ^ (r2 & 7)) << 4);

#define STAGE(BUF, KC)                                                              \
    do {                                                                            \
        int k0_ = (KC) * 32;                                                        \
        uint32_t bbuf = smb + (BUF) * BUFSZ;                                        \
        cpa16(bbuf + adof0,        wA1 + (size_t)ar0 * C + k0_ + acb0 * 8);         \
        cpa16(bbuf + adof1,        wA1 + (size_t)ar1 * C + k0_ + acb1 * 8);         \
        cpa16(bbuf + 8192 + adof0, wA2 + (size_t)ar0 * C + k0_ + acb0 * 8);         \
        cpa16(bbuf + 8192 + adof1, wA2 + (size_t)ar1 * C + k0_ + acb1 * 8);         \
        _Pragma("unroll")                                                           \
        for (int t = 0; t < 4; t++) {                                               \
            int slot = tid + t * 256;                                               \
            int rr   = slot >> 5;                                                   \
            int c4   = (slot & 31) * 4;                                             \
            if (p0 + c4 < HW)                                                       \
                cpa16(bbuf + 32768 + slot * 16,                                     \
                      xf + (size_t)(k0_ + rr) * HW + p0 + c4);                      \
            else                                                                    \
                *(uint4*)(smp + (BUF) * BUFSZ + 32768 + slot * 16) =                \
                    make_uint4(0, 0, 0, 0);                                         \
        }                                                                           \
        asm volatile("cp.async.commit_group;");                                     \
    } while (0)

    STAGE(0, 0);

    int cur = 0;
    for (int kc = 0; kc < NC; kc++) {
        asm volatile("cp.async.wait_group 0;");
        __syncthreads();

        {
            char* bufp = smp + cur * BUFSZ;
            const float* xs = (const float*)(bufp + 32768) + r2 * 128 + cg;
            float v[16];
            *(float4*)&v[0]  = *(const float4*)(xs + 0);
            *(float4*)&v[4]  = *(const float4*)(xs + 4);
            *(float4*)&v[8]  = *(const float4*)(xs + 8);
            *(float4*)&v[12] = *(const float4*)(xs + 12);
            uint4 h0, l0, h1, l1;
            split8(v,     &h0, &l0);
            split8(v + 8, &h1, &l1);
            *(uint4*)(bufp + 16384 + bo0) = h0;
            *(uint4*)(bufp + 16384 + bo1) = h1;
            *(uint4*)(bufp + 24576 + bo0) = l0;
            *(uint4*)(bufp + 24576 + bo1) = l1;
        }
        __syncthreads();

        if (kc + 1 < NC) STAGE(cur ^ 1, kc + 1);

        uint32_t base = smb + cur * BUFSZ;
#pragma unroll
        for (int ks = 0; ks < 2; ks++) {
            uint32_t bhf[2][4], blf[2][4];
            int brow = ks * 16 + (lane & 15);
            int nbb  = (n_off >> 3) + (lane >> 4);
#pragma unroll
            for (int nip = 0; nip < 2; nip++) {
                uint32_t boff = brow * 256 + (((nbb + nip * 2) ^ (brow & 7)) << 4);
                ldm_x4t(bhf[nip], base + 16384 + boff);
                ldm_x4t(blf[nip], base + 24576 + boff);
            }
#pragma unroll
            for (int mi = 0; mi < 4; mi++) {
                int arow = m_off + mi * 16 + (lane & 15);
                int cb   = ks * 2 + (lane >> 4);
                uint32_t aoff = arow * 64 + ((cb ^ ((arow >> 1) & 3)) << 4);
                uint32_t ah[4], al[4];
                ldm_x4(ah, base + aoff);
                ldm_x4(al, base + 8192 + aoff);
#pragma unroll
                for (int ni = 0; ni < 4; ni++) {
                    const uint32_t* bh = &bhf[ni >> 1][(ni & 1) * 2];
                    const uint32_t* bl = &blf[ni >> 1][(ni & 1) * 2];
                    mma16(acc[mi][ni], ah, bh);
                    mma16(acc[mi][ni], ah, bl);
                    mma16(acc[mi][ni], al, bh);
                }
            }
        }
        cur ^= 1;
    }

    const float* gg  = P.gg[lvl];
    const float* bbp = P.bb[lvl];
    const float* mm  = P.mm[lvl];
    const float* vv  = P.vv[lvl];
    float*       pf  = P.pf[lvl];
#pragma unroll
    for (int mi = 0; mi < 4; mi++) {
        int r0 = d0 + m_off + mi * 16 + g;
        int r1 = r0 + 8;
        float sc0 = gg[r0] * (1.0f / sqrtf(vv[r0] + 1e-5f));
        float bi0 = bbp[r0] - mm[r0] * sc0;
        float sc1 = gg[r1] * (1.0f / sqrtf(vv[r1] + 1e-5f));
        float bi1 = bbp[r1] - mm[r1] * sc1;
        float* op0 = pf + ((size_t)n * C + r0) * HW;
        float* op1 = pf + ((size_t)n * C + r1) * HW;
#pragma unroll
        for (int ni = 0; ni < 4; ni++) {
            int p = p0 + n_off + ni * 8 + 2 * tg;
            if (p < HW) {
                *(float2*)(op0 + p) = make_float2(silu(acc[mi][ni][0] * sc0 + bi0),
                                                  silu(acc[mi][ni][1] * sc0 + bi0));
                *(float2*)(op1 + p) = make_float2(silu(acc[mi][ni][2] * sc1 + bi1),
                                                  silu(acc[mi][ni][3] * sc1 + bi1));
            }
        }
    }
}

// ---------------- corr: merged, 3-stage shfl + 4-lane partial store ---------------
// wred layout: [pair][NW*4 slots][NS], slot = wid*4 + (lane&3)
template<int C, int H, int W, int STEP, int NG, int WINL>
__device__ __forceinline__ void corr_body(
    float* sm, const float* __restrict__ pf, const float* __restrict__ mlpw,
    float* __restrict__ out, int out_off, int c, int b)
{
    constexpr int PAD = RAD * STEP;
    constexpr int W2  = W + 2 * PAD;
    constexpr int H2  = H + 2 * PAD;
    constexpr int HW  = H * W;
    constexpr int NT  = 256;
    constexpr int NW  = 8;
    constexpr int NSL = NW * 4;          // 32 partial slots per pair

    float* f1p  = sm;
    float* wred = sm + H2 * W2;

    const int n1   = b * TPP + (TPP - 1);
    const int n2a  = g_idx[b * TFF + 0];
    const int n2b  = g_idx[b * TFF + 1];
    const int tid  = threadIdx.x;
    const int wid  = tid >> 5;
    const int lane = tid & 31;
    const int slot = wid * 4 + (lane & 3);
    const bool wr4 = (lane < 4);

    const float* f1g = pf + ((size_t)n1  * C + c) * HW;
    const float* f2a = pf + ((size_t)n2a * C + c) * HW;
    const float* f2b = pf + ((size_t)n2b * C + c) * HW;

    for (int q = tid; q < H2 * W2; q += NT) {
        int hh = q / W2 - PAD;
        int ww = q % W2 - PAD;
        float v = 0.f;
        if ((unsigned)hh < (unsigned)H && (unsigned)ww < (unsigned)W)
            v = f1g[hh * W + ww];
        f1p[q] = v;
    }

    float fra[NG][4], frb[NG][4];
    int   basek[NG];
#pragma unroll
    for (int gi = 0; gi < NG; gi++) {
        int p = (tid + NT * gi) * 4;
        if (p < HW) {
            float4 va = *(const float4*)(f2a + p);
            float4 vb = *(const float4*)(f2b + p);
            fra[gi][0] = va.x; fra[gi][1] = va.y; fra[gi][2] = va.z; fra[gi][3] = va.w;
            frb[gi][0] = vb.x; frb[gi][1] = vb.y; frb[gi][2] = vb.z; frb[gi][3] = vb.w;
            basek[gi] = (p / W + PAD) * W2 + (p % W) + PAD;
        } else {
#pragma unroll
            for (int v = 0; v < 4; v++) { fra[gi][v] = 0.f; frb[gi][v] = 0.f; }
            basek[gi] = PAD * W2 + PAD;
        }
    }
    __syncthreads();

#define RED_STORE(OFF)                                                             \
    do {                                                                           \
        va += __shfl_xor_sync(0xffffffffu, va, 16);                                \
        vb += __shfl_xor_sync(0xffffffffu, vb, 16);                                \
        va += __shfl_xor_sync(0xffffffffu, va, 8);                                 \
        vb += __shfl_xor_sync(0xffffffffu, vb, 8);                                 \
        va += __shfl_xor_sync(0xffffffffu, va, 4);                                 \
        vb += __shfl_xor_sync(0xffffffffu, vb, 4);                                 \
        if (wr4) {                                                                 \
            wred[(0 * NSL + slot) * NS + (OFF)] = va;                              \
            wred[(1 * NSL + slot) * NS + (OFF)] = vb;                              \
        }                                                                          \
    } while (0)

    if (WINL == 0) {
        for (int oy = 0; oy < 9; oy++) {
            int ro[NG];
            int dyo = (oy - RAD) * STEP * W2;
#pragma unroll
            for (int gi = 0; gi < NG; gi++) ro[gi] = basek[gi] + dyo;
#pragma unroll
            for (int ox = 0; ox < 9; ox++) {
                const int dxo = (ox - RAD) * STEP;
                float a0 = 0.f, a1 = 0.f, b0 = 0.f, b1 = 0.f;
#pragma unroll
                for (int gi = 0; gi < NG; gi++) {
                    float4 fv = *(const float4*)&f1p[ro[gi] + dxo];
                    a0 = fmaf(fv.x, fra[gi][0], a0);
                    a1 = fmaf(fv.y, fra[gi][1], a1);
                    a0 = fmaf(fv.z, fra[gi][2], a0);
                    a1 = fmaf(fv.w, fra[gi][3], a1);
                    b0 = fmaf(fv.x, frb[gi][0], b0);
                    b1 = fmaf(fv.y, frb[gi][1], b1);
                    b0 = fmaf(fv.z, frb[gi][2], b0);
                    b1 = fmaf(fv.w, frb[gi][3], b1);
                }
                float va = a0 + a1, vb = b0 + b1;
                RED_STORE(oy * 9 + ox);
            }
        }
    } else {
        for (int oy = 0; oy < 9; oy++) {
            int dyo = (oy - RAD) * STEP * W2;
            float aA[9], aB[9];
#pragma unroll
            for (int ox = 0; ox < 9; ox++) { aA[ox] = 0.f; aB[ox] = 0.f; }
#pragma unroll
            for (int gi = 0; gi < NG; gi++) {
                const float* wp = &f1p[basek[gi] + dyo - 4 * STEP];
                float win[WINL > 0 ? WINL : 1];
#pragma unroll
                for (int t = 0; t < WINL / 4; t++) {
                    float4 v = *(const float4*)(wp + 4 * t);
                    win[4 * t] = v.x; win[4 * t + 1] = v.y;
                    win[4 * t + 2] = v.z; win[4 * t + 3] = v.w;
                }
#pragma unroll
                for (int ox = 0; ox < 9; ox++) {
#pragma unroll
                    for (int j = 0; j < 4; j++) {
                        aA[ox] = fmaf(win[STEP * ox + j], fra[gi][j], aA[ox]);
                        aB[ox] = fmaf(win[STEP * ox + j], frb[gi][j], aB[ox]);
                    }
                }
            }
#pragma unroll
            for (int ox = 0; ox < 9; ox++) {
                float va = aA[ox], vb = aB[ox];
                RED_STORE(oy * 9 + ox);
            }
        }
    }
#undef RED_STORE
    __syncthreads();

    if (tid < 64) {
        int q = tid >> 5, l = tid & 31;
        const float* wr = wred + q * NSL * NS;
        float v0, v1 = -1e30f, v2 = -1e30f;
        {
            float s0 = 0.f, s1 = 0.f, s2 = 0.f;
#pragma unroll 4
            for (int w = 0; w < NSL; w++) {
                s0 += wr[w * NS + l];
                if (l + 32 < NS) s1 += wr[w * NS + l + 32];
                if (l + 64 < NS) s2 += wr[w * NS + l + 64];
            }
            v0 = s0;
            if (l + 32 < NS) v1 = s1;
            if (l + 64 < NS) v2 = s2;
        }
        float mx = fmaxf(v0, fmaxf(v1, v2));
#pragma unroll
        for (int o = 16; o; o >>= 1)
            mx = fmaxf(mx, __shfl_xor_sync(0xffffffffu, mx, o));
        float e0 = expf(v0 - mx);
        float e1 = (l + 32 < NS) ? expf(v1 - mx) : 0.f;
        float e2 = (l + 64 < NS) ? expf(v2 - mx) : 0.f;
        float w0 = mlpw[l];
        float w1 = (l + 32 < NS) ? mlpw[l + 32] : 0.f;
        float w2 = (l + 64 < NS) ? mlpw[l + 64] : 0.f;
        float ssum = e0 + e1 + e2;
        float dot  = e0 * w0 + e1 * w1 + e2 * w2;
#pragma unroll
        for (int o = 16; o; o >>= 1) {
            ssum += __shfl_xor_sync(0xffffffffu, ssum, o);
            dot  += __shfl_xor_sync(0xffffffffu, dot,  o);
        }
        if (l == 0)
            out[out_off + (b * TFF + q) * C + c] = dot / ssum;
    }
}

__global__ void __launch_bounds__(256, 3) corr_all(
    const float* __restrict__ pf0, const float* __restrict__ pf1,
    const float* __restrict__ pf2, const float* __restrict__ mlpw,
    float* __restrict__ out)
{
    extern __shared__ float smf[];
    int i = blockIdx.x;
    if (i < 512) {
        corr_body<128, 80, 80, 4, 7,  0>(smf, pf0, mlpw, out, 0,    i >> 2, i & 3);
    } else if (i < 1536) {
        int j = i - 512;
        corr_body<256, 40, 40, 2, 2, 20>(smf, pf1, mlpw, out, 1024, j >> 2, j & 3);
    } else {
        int j = i - 1536;
        corr_body<512, 20, 20, 1, 1, 12>(smf, pf2, mlpw, out, 3072, j >> 2, j & 3);
    }
}

// ---------------- launch ----------------------------------------------------------
extern "C" void kernel_launch(void* const* d_in, const int* in_sizes, int n_in,
                              void* d_out, int out_size)
{
    int map_sig [21] = {0,1,2, 3,4,5,6,7, 8,9,10,11,12, 13,14,15,16,17, 18,19,20};
    int map_dict[21] = {0,6,12, 1,2,3,4,5, 7,8,9,10,11, 13,14,15,16,17, 18,19,20};
    const int* map = (in_sizes[1] == 16384) ? map_dict : map_sig;

    const float* mlpw = (const float*)d_in[map[18]];
    const int*   pci  = (const int*)d_in[map[19]];
    const int*   fci  = (const int*)d_in[map[20]];
    float* out = (float*)d_out;

    void* pv;
    cudaGetSymbolAddress(&pv, g_pf0);  float* pf0 = (float*)pv;
    cudaGetSymbolAddress(&pv, g_pf1);  float* pf1 = (float*)pv;
    cudaGetSymbolAddress(&pv, g_pf2);  float* pf2 = (float*)pv;
    __nv_bfloat16 *w0a, *w0b, *w1a, *w1b, *w2a, *w2b;
    cudaGetSymbolAddress(&pv, g_w0a); w0a = (__nv_bfloat16*)pv;
    cudaGetSymbolAddress(&pv, g_w0b); w0b = (__nv_bfloat16*)pv;
    cudaGetSymbolAddress(&pv, g_w1a); w1a = (__nv_bfloat16*)pv;
    cudaGetSymbolAddress(&pv, g_w1b); w1b = (__nv_bfloat16*)pv;
    cudaGetSymbolAddress(&pv, g_w2a); w2a = (__nv_bfloat16*)pv;
    cudaGetSymbolAddress(&pv, g_w2b); w2b = (__nv_bfloat16*)pv;

    prep_kernel<<<1, 1>>>(pci, fci);

    SplitW SW;
    SW.w[0] = (const float*)d_in[map[3]];
    SW.w[1] = (const float*)d_in[map[8]];
    SW.w[2] = (const float*)d_in[map[13]];
    SW.wa[0] = w0a; SW.wa[1] = w1a; SW.wa[2] = w2a;
    SW.wb[0] = w0b; SW.wb[1] = w1b; SW.wb[2] = w2b;
    wsplit_all<<<dim3(128, 3), 256>>>(SW);

    ConvTC P;
    P.wa[0] = w0a; P.wa[1] = w1a; P.wa[2] = w2a;
    P.wb[0] = w0b; P.wb[1] = w1b; P.wb[2] = w2b;
    P.x[0] = (const float*)d_in[map[0]];
    P.x[1] = (const float*)d_in[map[1]];
    P.x[2] = (const float*)d_in[map[2]];
    P.gg[0] = (const float*)d_in[map[4]];  P.gg[1] = (const float*)d_in[map[9]];   P.gg[2] = (const float*)d_in[map[14]];
    P.bb[0] = (const float*)d_in[map[5]];  P.bb[1] = (const float*)d_in[map[10]];  P.bb[2] = (const float*)d_in[map[15]];
    P.mm[0] = (const float*)d_in[map[6]];  P.mm[1] = (const float*)d_in[map[11]];  P.mm[2] = (const float*)d_in[map[16]];
    P.vv[0] = (const float*)d_in[map[7]];  P.vv[1] = (const float*)d_in[map[12]];  P.vv[2] = (const float*)d_in[map[17]];
    P.pf[0] = pf0; P.pf[1] = pf1; P.pf[2] = pf2;

    cudaFuncSetAttribute(conv_bf16_kernel,
                         cudaFuncAttributeMaxDynamicSharedMemorySize, 2 * BUFSZ);
    conv_bf16_kernel<<<dim3(92, 1, NFR), 256, 2 * BUFSZ>>>(P);

    // dyn smem: lvl0 plane 112*112 + wred 2*32*81 floats = 70912 B
    size_t smc = (size_t)(112 * 112 + 2 * 32 * NS) * sizeof(float);
    cudaFuncSetAttribute(corr_all,
                         cudaFuncAttributeMaxDynamicSharedMemorySize, (int)smc);
    corr_all<<<3584, 256, smc>>>(pf0, pf1, pf2, mlpw, out);
}

// round 15
// speedup vs baseline: 1.4126x; 1.4126x over previous
#include <cuda_runtime.h>
#include <cuda_bf16.h>
#include <math.h>
#include <stdint.h>

#define BB    4
#define TPP   4
#define TFF   2
#define NPAIR (BB*TFF)
#define RAD   4
#define NS    81
#define NFR   (BB*TPP)

// ---------------- scratch ---------------------------------------------------------
__device__ int   g_idx[NPAIR];
__device__ int   g_needed[NFR];
__device__ float g_pf0[(size_t)NFR * 128 * 6400];
__device__ float g_pf1[(size_t)NFR * 256 * 1600];
__device__ float g_pf2[(size_t)NFR * 512 * 400];
__device__ __nv_bfloat16 g_w0a[128*128],  g_w0b[128*128];
__device__ __nv_bfloat16 g_w1a[256*256],  g_w1b[256*256];
__device__ __nv_bfloat16 g_w2a[512*512],  g_w2b[512*512];

// ---------------- W split + inline prep -------------------------------------------
union BV8 { __nv_bfloat16 h[8]; uint4 u; };

__device__ __forceinline__ void split8(const float* v, uint4* ua, uint4* ub)
{
    BV8 a, b;
#pragma unroll
    for (int j = 0; j < 8; j++) {
        __nv_bfloat16 h = __float2bfloat16(v[j]);
        a.h[j] = h;
        b.h[j] = __float2bfloat16(v[j] - __bfloat162float(h));
    }
    *ua = a.u; *ub = b.u;
}

struct SplitW {
    const float* w[3];
    __nv_bfloat16 *wa[3], *wb[3];
    const int* pci;
    const int* fci;
};

__global__ void wsplit_all(SplitW S)
{
    // prep (interp indices + needed flags) on one thread; conv/corr follow in
    // stream order so visibility is guaranteed.
    if (blockIdx.x == 0 && blockIdx.y == 0 && threadIdx.x == 0) {
        for (int n = 0; n < NFR; n++) g_needed[n] = 0;
        for (int i = 0; i < BB; i++) {
            int p_pos = TPP - 2;
            for (int j = 0; j < TFF; j++) {
                int f_i = S.fci[i * TFF + j];
                while (p_pos >= 0) {
                    if (p_pos == 0 || f_i < -S.pci[i * TPP + p_pos - 1]) {
                        int id = p_pos + i * TPP;
                        g_idx[i * TFF + j] = id;
                        g_needed[id] = 1;
                        break;
                    }
                    p_pos--;
                }
            }
            g_needed[i * TPP + (TPP - 1)] = 1;
        }
    }
    int lvl = blockIdx.y;
    int nE  = (128 << lvl) * (128 << lvl);
    int i   = (blockIdx.x * 256 + threadIdx.x) * 8;
    if (i < nE) {
        float v[8];
        *(float4*)&v[0] = *(const float4*)(S.w[lvl] + i);
        *(float4*)&v[4] = *(const float4*)(S.w[lvl] + i + 4);
        split8(v, (uint4*)(S.wa[lvl] + i), (uint4*)(S.wb[lvl] + i));
    }
}

// ---------------- mma.sync bf16 helpers -------------------------------------------
__device__ __forceinline__ uint32_t smem_u32(const void* p)
{
    uint32_t a;
    asm("{ .reg .u64 t; cvta.to.shared.u64 t, %1; cvt.u32.u64 %0, t; }" : "=r"(a) : "l"(p));
    return a;
}

__device__ __forceinline__ void ldm_x4(uint32_t* r, uint32_t addr)
{
    asm volatile("ldmatrix.sync.aligned.m8n8.x4.shared.b16 {%0,%1,%2,%3}, [%4];"
                 : "=r"(r[0]), "=r"(r[1]), "=r"(r[2]), "=r"(r[3]) : "r"(addr));
}

__device__ __forceinline__ void ldm_x4t(uint32_t* r, uint32_t addr)
{
    asm volatile("ldmatrix.sync.aligned.m8n8.x4.trans.shared.b16 {%0,%1,%2,%3}, [%4];"
                 : "=r"(r[0]), "=r"(r[1]), "=r"(r[2]), "=r"(r[3]) : "r"(addr));
}

__device__ __forceinline__ void mma16(float* c, const uint32_t* a, const uint32_t* b)
{
    asm volatile(
        "mma.sync.aligned.m16n8k16.row.col.f32.bf16.bf16.f32 "
        "{%0,%1,%2,%3}, {%4,%5,%6,%7}, {%8,%9}, {%0,%1,%2,%3};"
        : "+f"(c[0]), "+f"(c[1]), "+f"(c[2]), "+f"(c[3])
        : "r"(a[0]), "r"(a[1]), "r"(a[2]), "r"(a[3]), "r"(b[0]), "r"(b[1]));
}

__device__ __forceinline__ void cpa16(uint32_t dst, const void* src)
{
    asm volatile("cp.async.cg.shared.global [%0], [%1], 16;" :: "r"(dst), "l"(src));
}

__device__ __forceinline__ float silu(float y) { return y / (1.0f + expf(-y)); }

// ---------------- conv (R12 banked, STAGE moved before convert) -------------------
#define BUFSZ 49152

struct ConvTC {
    const __nv_bfloat16 *wa[3], *wb[3];
    const float *x[3];
    const float *gg[3], *bb[3], *mm[3], *vv[3];
    float *pf[3];
};

__global__ void __launch_bounds__(256, 2) conv_bf16_kernel(ConvTC P)
{
    int n = blockIdx.z;
    if (!g_needed[n]) return;

    int bx = blockIdx.x, lvl, p0, d0;
    if (bx < 50)      { lvl = 0; p0 = bx * 128; d0 = 0; }
    else if (bx < 76) { int r = bx - 50; lvl = 1; p0 = (r % 13) * 128; d0 = (r / 13) * 128; }
    else              { int r = bx - 76; lvl = 2; p0 = (r & 3) * 128;  d0 = (r >> 2) * 128; }
    const int C  = 128 << lvl;
    const int HW = 6400 >> (2 * lvl);
    const int NC = C >> 5;

    extern __shared__ uint32_t dsm[];
    char* smp = (char*)dsm;
    const int tid  = threadIdx.x;
    const int lane = tid & 31;
    const int wid  = tid >> 5;
    const int m_off = (wid & 1) * 64;
    const int n_off = (wid >> 1) * 32;
    const int g  = lane >> 2;
    const int tg = lane & 3;
    const uint32_t smb = smem_u32(dsm);

    const __nv_bfloat16* wA1 = P.wa[lvl] + (size_t)d0 * C;
    const __nv_bfloat16* wA2 = P.wb[lvl] + (size_t)d0 * C;
    const float*         xf  = P.x[lvl] + (size_t)n * C * HW;

    float acc[4][4][4];
#pragma unroll
    for (int mi = 0; mi < 4; mi++)
#pragma unroll
        for (int ni = 0; ni < 4; ni++)
#pragma unroll
            for (int r = 0; r < 4; r++) acc[mi][ni][r] = 0.f;

    const int ar0 = tid >> 2,          acb0 = tid & 3;
    const int ar1 = (tid + 256) >> 2,  acb1 = (tid + 256) & 3;
    const uint32_t adof0 = ar0 * 64 + ((acb0 ^ ((ar0 >> 1) & 3)) << 4);
    const uint32_t adof1 = ar1 * 64 + ((acb1 ^ ((ar1 >> 1) & 3)) << 4);

    const int r2  = tid >> 3;
    const int cg  = (tid & 7) * 16;
    const int nb0 = (tid & 7) * 2;
    const uint32_t bo0 = r2 * 256 + ((nb0 ^ (r2 & 7)) << 4);
    const uint32_t bo1 = r2 * 256 + (((nb0 + 1) ^ (r2 & 7)) << 4);

#define STAGE(BUF, KC)                                                              \
    do {                                                                            \
        int k0_ = (KC) * 32;                                                        \
        uint32_t bbuf = smb + (BUF) * BUFSZ;                                        \
        cpa16(bbuf + adof0,        wA1 + (size_t)ar0 * C + k0_ + acb0 * 8);         \
        cpa16(bbuf + adof1,        wA1 + (size_t)ar1 * C + k0_ + acb1 * 8);         \
        cpa16(bbuf + 8192 + adof0, wA2 + (size_t)ar0 * C + k0_ + acb0 * 8);         \
        cpa16(bbuf + 8192 + adof1, wA2 + (size_t)ar1 * C + k0_ + acb1 * 8);         \
        _Pragma("unroll")                                                           \
        for (int t = 0; t < 4; t++) {                                               \
            int slot = tid + t * 256;                                               \
            int rr   = slot >> 5;                                                   \
            int c4   = (slot & 31) * 4;                                             \
            if (p0 + c4 < HW)                                                       \
                cpa16(bbuf + 32768 + slot * 16,                                     \
                      xf + (size_t)(k0_ + rr) * HW + p0 + c4);                      \
            else                                                                    \
                *(uint4*)(smp + (BUF) * BUFSZ + 32768 + slot * 16) =                \
                    make_uint4(0, 0, 0, 0);                                         \
        }                                                                           \
        asm volatile("cp.async.commit_group;");                                     \
    } while (0)

    STAGE(0, 0);

    int cur = 0;
    for (int kc = 0; kc < NC; kc++) {
        if (kc + 1 < NC) {
            // wait only for buffer cur (the older group); next-group may be issued below
            asm volatile("cp.async.wait_group 0;");
        } else {
            asm volatile("cp.async.wait_group 0;");
        }
        __syncthreads();

        // issue next chunk's staging BEFORE the convert phase (targets buffer nxt)
        if (kc + 1 < NC) STAGE(cur ^ 1, kc + 1);

        {
            char* bufp = smp + cur * BUFSZ;
            const float* xs = (const float*)(bufp + 32768) + r2 * 128 + cg;
            float v[16];
            *(float4*)&v[0]  = *(const float4*)(xs + 0);
            *(float4*)&v[4]  = *(const float4*)(xs + 4);
            *(float4*)&v[8]  = *(const float4*)(xs + 8);
            *(float4*)&v[12] = *(const float4*)(xs + 12);
            uint4 h0, l0, h1, l1;
            split8(v,     &h0, &l0);
            split8(v + 8, &h1, &l1);
            *(uint4*)(bufp + 16384 + bo0) = h0;
            *(uint4*)(bufp + 16384 + bo1) = h1;
            *(uint4*)(bufp + 24576 + bo0) = l0;
            *(uint4*)(bufp + 24576 + bo1) = l1;
        }
        __syncthreads();

        uint32_t base = smb + cur * BUFSZ;
#pragma unroll
        for (int ks = 0; ks < 2; ks++) {
            uint32_t bhf[2][4], blf[2][4];
            int brow = ks * 16 + (lane & 15);
            int nbb  = (n_off >> 3) + (lane >> 4);
#pragma unroll
            for (int nip = 0; nip < 2; nip++) {
                uint32_t boff = brow * 256 + (((nbb + nip * 2) ^ (brow & 7)) << 4);
                ldm_x4t(bhf[nip], base + 16384 + boff);
                ldm_x4t(blf[nip], base + 24576 + boff);
            }
#pragma unroll
            for (int mi = 0; mi < 4; mi++) {
                int arow = m_off + mi * 16 + (lane & 15);
                int cb   = ks * 2 + (lane >> 4);
                uint32_t aoff = arow * 64 + ((cb ^ ((arow >> 1) & 3)) << 4);
                uint32_t ah[4], al[4];
                ldm_x4(ah, base + aoff);
                ldm_x4(al, base + 8192 + aoff);
#pragma unroll
                for (int ni = 0; ni < 4; ni++) {
                    const uint32_t* bh = &bhf[ni >> 1][(ni & 1) * 2];
                    const uint32_t* bl = &blf[ni >> 1][(ni & 1) * 2];
                    mma16(acc[mi][ni], ah, bh);
                    mma16(acc[mi][ni], ah, bl);
                    mma16(acc[mi][ni], al, bh);
                }
            }
        }
        cur ^= 1;
    }

    const float* gg  = P.gg[lvl];
    const float* bbp = P.bb[lvl];
    const float* mm  = P.mm[lvl];
    const float* vv  = P.vv[lvl];
    float*       pf  = P.pf[lvl];
#pragma unroll
    for (int mi = 0; mi < 4; mi++) {
        int r0 = d0 + m_off + mi * 16 + g;
        int r1 = r0 + 8;
        float sc0 = gg[r0] * (1.0f / sqrtf(vv[r0] + 1e-5f));
        float bi0 = bbp[r0] - mm[r0] * sc0;
        float sc1 = gg[r1] * (1.0f / sqrtf(vv[r1] + 1e-5f));
        float bi1 = bbp[r1] - mm[r1] * sc1;
        float* op0 = pf + ((size_t)n * C + r0) * HW;
        float* op1 = pf + ((size_t)n * C + r1) * HW;
#pragma unroll
        for (int ni = 0; ni < 4; ni++) {
            int p = p0 + n_off + ni * 8 + 2 * tg;
            if (p < HW) {
                *(float2*)(op0 + p) = make_float2(silu(acc[mi][ni][0] * sc0 + bi0),
                                                  silu(acc[mi][ni][1] * sc0 + bi0));
                *(float2*)(op1 + p) = make_float2(silu(acc[mi][ni][2] * sc1 + bi1),
                                                  silu(acc[mi][ni][3] * sc1 + bi1));
            }
        }
    }
}

// ---------------- corr: merged levels (R13 banked) --------------------------------
template<int C, int H, int W, int STEP, int NG, int WINL>
__device__ __forceinline__ void corr_body(
    float* sm, const float* __restrict__ pf, const float* __restrict__ mlpw,
    float* __restrict__ out, int out_off, int c, int b)
{
    constexpr int PAD = RAD * STEP;
    constexpr int W2  = W + 2 * PAD;
    constexpr int H2  = H + 2 * PAD;
    constexpr int HW  = H * W;
    constexpr int NT  = 256;
    constexpr int NW  = 8;

    float* f1p  = sm;
    float* wred = sm + H2 * W2;

    const int n1   = b * TPP + (TPP - 1);
    const int n2a  = g_idx[b * TFF + 0];
    const int n2b  = g_idx[b * TFF + 1];
    const int tid  = threadIdx.x;
    const int wid  = tid >> 5;
    const int lane = tid & 31;

    const float* f1g = pf + ((size_t)n1  * C + c) * HW;
    const float* f2a = pf + ((size_t)n2a * C + c) * HW;
    const float* f2b = pf + ((size_t)n2b * C + c) * HW;

    for (int q = tid; q < H2 * W2; q += NT) {
        int hh = q / W2 - PAD;
        int ww = q % W2 - PAD;
        float v = 0.f;
        if ((unsigned)hh < (unsigned)H && (unsigned)ww < (unsigned)W)
            v = f1g[hh * W + ww];
        f1p[q] = v;
    }

    float fra[NG][4], frb[NG][4];
    int   basek[NG];
#pragma unroll
    for (int gi = 0; gi < NG; gi++) {
        int p = (tid + NT * gi) * 4;
        if (p < HW) {
            float4 va = *(const float4*)(f2a + p);
            float4 vb = *(const float4*)(f2b + p);
            fra[gi][0] = va.x; fra[gi][1] = va.y; fra[gi][2] = va.z; fra[gi][3] = va.w;
            frb[gi][0] = vb.x; frb[gi][1] = vb.y; frb[gi][2] = vb.z; frb[gi][3] = vb.w;
            basek[gi] = (p / W + PAD) * W2 + (p % W) + PAD;
        } else {
#pragma unroll
            for (int v = 0; v < 4; v++) { fra[gi][v] = 0.f; frb[gi][v] = 0.f; }
            basek[gi] = PAD * W2 + PAD;
        }
    }
    __syncthreads();

    if (WINL == 0) {
        for (int oy = 0; oy < 9; oy++) {
            int ro[NG];
            int dyo = (oy - RAD) * STEP * W2;
#pragma unroll
            for (int gi = 0; gi < NG; gi++) ro[gi] = basek[gi] + dyo;
#pragma unroll
            for (int ox = 0; ox < 9; ox++) {
                const int dxo = (ox - RAD) * STEP;
                float a0 = 0.f, a1 = 0.f, b0 = 0.f, b1 = 0.f;
#pragma unroll
                for (int gi = 0; gi < NG; gi++) {
                    float4 fv = *(const float4*)&f1p[ro[gi] + dxo];
                    a0 = fmaf(fv.x, fra[gi][0], a0);
                    a1 = fmaf(fv.y, fra[gi][1], a1);
                    a0 = fmaf(fv.z, fra[gi][2], a0);
                    a1 = fmaf(fv.w, fra[gi][3], a1);
                    b0 = fmaf(fv.x, frb[gi][0], b0);
                    b1 = fmaf(fv.y, frb[gi][1], b1);
                    b0 = fmaf(fv.z, frb[gi][2], b0);
                    b1 = fmaf(fv.w, frb[gi][3], b1);
                }
                float va = a0 + a1, vb = b0 + b1;
#pragma unroll
                for (int o = 16; o; o >>= 1) {
                    va += __shfl_xor_sync(0xffffffffu, va, o);
                    vb += __shfl_xor_sync(0xffffffffu, vb, o);
                }
                if (lane == 0) {
                    wred[(0 * NW + wid) * NS + oy * 9 + ox] = va;
                    wred[(1 * NW + wid) * NS + oy * 9 + ox] = vb;
                }
            }
        }
    } else {
        for (int oy = 0; oy < 9; oy++) {
            int dyo = (oy - RAD) * STEP * W2;
            float aA[9], aB[9];
#pragma unroll
            for (int ox = 0; ox < 9; ox++) { aA[ox] = 0.f; aB[ox] = 0.f; }
#pragma unroll
            for (int gi = 0; gi < NG; gi++) {
                const float* wp = &f1p[basek[gi] + dyo - 4 * STEP];
                float win[WINL > 0 ? WINL : 1];
#pragma unroll
                for (int t = 0; t < WINL / 4; t++) {
                    float4 v = *(const float4*)(wp + 4 * t);
                    win[4 * t] = v.x; win[4 * t + 1] = v.y;
                    win[4 * t + 2] = v.z; win[4 * t + 3] = v.w;
                }
#pragma unroll
                for (int ox = 0; ox < 9; ox++) {
#pragma unroll
                    for (int j = 0; j < 4; j++) {
                        aA[ox] = fmaf(win[STEP * ox + j], fra[gi][j], aA[ox]);
                        aB[ox] = fmaf(win[STEP * ox + j], frb[gi][j], aB[ox]);
                    }
                }
            }
#pragma unroll
            for (int ox = 0; ox < 9; ox++) {
                float va = aA[ox], vb = aB[ox];
#pragma unroll
                for (int o = 16; o; o >>= 1) {
                    va += __shfl_xor_sync(0xffffffffu, va, o);
                    vb += __shfl_xor_sync(0xffffffffu, vb, o);
                }
                if (lane == 0) {
                    wred[(0 * NW + wid) * NS + oy * 9 + ox] = va;
                    wred[(1 * NW + wid) * NS + oy * 9 + ox] = vb;
                }
            }
        }
    }
    __syncthreads();

    if (tid < 64) {
        int q = tid >> 5, l = tid & 31;
        const float* wr = wred + q * NW * NS;
        float v0, v1 = -1e30f, v2 = -1e30f;
        {
            float s0 = 0.f, s1 = 0.f, s2 = 0.f;
#pragma unroll
            for (int w = 0; w < NW; w++) {
                s0 += wr[w * NS + l];
                if (l + 32 < NS) s1 += wr[w * NS + l + 32];
                if (l + 64 < NS) s2 += wr[w * NS + l + 64];
            }
            v0 = s0;
            if (l + 32 < NS) v1 = s1;
            if (l + 64 < NS) v2 = s2;
        }
        float mx = fmaxf(v0, fmaxf(v1, v2));
#pragma unroll
        for (int o = 16; o; o >>= 1)
            mx = fmaxf(mx, __shfl_xor_sync(0xffffffffu, mx, o));
        float e0 = expf(v0 - mx);
        float e1 = (l + 32 < NS) ? expf(v1 - mx) : 0.f;
        float e2 = (l + 64 < NS) ? expf(v2 - mx) : 0.f;
        float w0 = mlpw[l];
        float w1 = (l + 32 < NS) ? mlpw[l + 32] : 0.f;
        float w2 = (l + 64 < NS) ? mlpw[l + 64] : 0.f;
        float ssum = e0 + e1 + e2;
        float dot  = e0 * w0 + e1 * w1 + e2 * w2;
#pragma unroll
        for (int o = 16; o; o >>= 1) {
            ssum += __shfl_xor_sync(0xffffffffu, ssum, o);
            dot  += __shfl_xor_sync(0xffffffffu, dot,  o);
        }
        if (l == 0)
            out[out_off + (b * TFF + q) * C + c] = dot / ssum;
    }
}

__global__ void __launch_bounds__(256, 3) corr_all(
    const float* __restrict__ pf0, const float* __restrict__ pf1,
    const float* __restrict__ pf2, const float* __restrict__ mlpw,
    float* __restrict__ out)
{
    extern __shared__ float smf[];
    int i = blockIdx.x;
    if (i < 512) {
        corr_body<128, 80, 80, 4, 7,  0>(smf, pf0, mlpw, out, 0,    i >> 2, i & 3);
    } else if (i < 1536) {
        int j = i - 512;
        corr_body<256, 40, 40, 2, 2, 20>(smf, pf1, mlpw, out, 1024, j >> 2, j & 3);
    } else {
        int j = i - 1536;
        corr_body<512, 20, 20, 1, 1, 12>(smf, pf2, mlpw, out, 3072, j >> 2, j & 3);
    }
}

// ---------------- launch ----------------------------------------------------------
extern "C" void kernel_launch(void* const* d_in, const int* in_sizes, int n_in,
                              void* d_out, int out_size)
{
    int map_sig [21] = {0,1,2, 3,4,5,6,7, 8,9,10,11,12, 13,14,15,16,17, 18,19,20};
    int map_dict[21] = {0,6,12, 1,2,3,4,5, 7,8,9,10,11, 13,14,15,16,17, 18,19,20};
    const int* map = (in_sizes[1] == 16384) ? map_dict : map_sig;

    const float* mlpw = (const float*)d_in[map[18]];
    const int*   pci  = (const int*)d_in[map[19]];
    const int*   fci  = (const int*)d_in[map[20]];
    float* out = (float*)d_out;

    void* pv;
    cudaGetSymbolAddress(&pv, g_pf0);  float* pf0 = (float*)pv;
    cudaGetSymbolAddress(&pv, g_pf1);  float* pf1 = (float*)pv;
    cudaGetSymbolAddress(&pv, g_pf2);  float* pf2 = (float*)pv;
    __nv_bfloat16 *w0a, *w0b, *w1a, *w1b, *w2a, *w2b;
    cudaGetSymbolAddress(&pv, g_w0a); w0a = (__nv_bfloat16*)pv;
    cudaGetSymbolAddress(&pv, g_w0b); w0b = (__nv_bfloat16*)pv;
    cudaGetSymbolAddress(&pv, g_w1a); w1a = (__nv_bfloat16*)pv;
    cudaGetSymbolAddress(&pv, g_w1b); w1b = (__nv_bfloat16*)pv;
    cudaGetSymbolAddress(&pv, g_w2a); w2a = (__nv_bfloat16*)pv;
    cudaGetSymbolAddress(&pv, g_w2b); w2b = (__nv_bfloat16*)pv;

    SplitW SW;
    SW.w[0] = (const float*)d_in[map[3]];
    SW.w[1] = (const float*)d_in[map[8]];
    SW.w[2] = (const float*)d_in[map[13]];
    SW.wa[0] = w0a; SW.wa[1] = w1a; SW.wa[2] = w2a;
    SW.wb[0] = w0b; SW.wb[1] = w1b; SW.wb[2] = w2b;
    SW.pci = pci; SW.fci = fci;
    wsplit_all<<<dim3(128, 3), 256>>>(SW);

    ConvTC P;
    P.wa[0] = w0a; P.wa[1] = w1a; P.wa[2] = w2a;
    P.wb[0] = w0b; P.wb[1] = w1b; P.wb[2] = w2b;
    P.x[0] = (const float*)d_in[map[0]];
    P.x[1] = (const float*)d_in[map[1]];
    P.x[2] = (const float*)d_in[map[2]];
    P.gg[0] = (const float*)d_in[map[4]];  P.gg[1] = (const float*)d_in[map[9]];   P.gg[2] = (const float*)d_in[map[14]];
    P.bb[0] = (const float*)d_in[map[5]];  P.bb[1] = (const float*)d_in[map[10]];  P.bb[2] = (const float*)d_in[map[15]];
    P.mm[0] = (const float*)d_in[map[6]];  P.mm[1] = (const float*)d_in[map[11]];  P.mm[2] = (const float*)d_in[map[16]];
    P.vv[0] = (const float*)d_in[map[7]];  P.vv[1] = (const float*)d_in[map[12]];  P.vv[2] = (const float*)d_in[map[17]];
    P.pf[0] = pf0; P.pf[1] = pf1; P.pf[2] = pf2;

    cudaFuncSetAttribute(conv_bf16_kernel,
                         cudaFuncAttributeMaxDynamicSharedMemorySize, 2 * BUFSZ);
    conv_bf16_kernel<<<dim3(92, 1, NFR), 256, 2 * BUFSZ>>>(P);

    size_t smc = (size_t)(112 * 112 + 2 * 8 * NS) * sizeof(float);   // ~55.4 KB
    cudaFuncSetAttribute(corr_all,
                         cudaFuncAttributeMaxDynamicSharedMemorySize, 65536);
    corr_all<<<3584, 256, smc>>>(pf0, pf1, pf2, mlpw, out);
}

// round 16
// speedup vs baseline: 1.4275x; 1.0106x over previous
#include <cuda_runtime.h>
#include <cuda_bf16.h>
#include <math.h>
#include <stdint.h>

#define BB    4
#define TPP   4
#define TFF   2
#define NPAIR (BB*TFF)
#define RAD   4
#define NS    81
#define NFR   (BB*TPP)

// ---------------- scratch ---------------------------------------------------------
__device__ int   g_idx[NPAIR];
__device__ int   g_needed[NFR];
__device__ float g_pf0[(size_t)NFR * 128 * 6400];
__device__ float g_pf1[(size_t)NFR * 256 * 1600];
__device__ float g_pf2[(size_t)NFR * 512 * 400];
__device__ __nv_bfloat16 g_w0a[128*128],  g_w0b[128*128];
__device__ __nv_bfloat16 g_w1a[256*256],  g_w1b[256*256];
__device__ __nv_bfloat16 g_w2a[512*512],  g_w2b[512*512];

// ---------------- prep ------------------------------------------------------------
__global__ void prep_kernel(const int* __restrict__ pci, const int* __restrict__ fci)
{
    if (threadIdx.x != 0 || blockIdx.x != 0) return;
    for (int n = 0; n < NFR; n++) g_needed[n] = 0;
    for (int i = 0; i < BB; i++) {
        int p_pos = TPP - 2;
        for (int j = 0; j < TFF; j++) {
            int f_i = fci[i * TFF + j];
            while (p_pos >= 0) {
                if (p_pos == 0 || f_i < -pci[i * TPP + p_pos - 1]) {
                    int id = p_pos + i * TPP;
                    g_idx[i * TFF + j] = id;
                    g_needed[id] = 1;
                    break;
                }
                p_pos--;
            }
        }
        g_needed[i * TPP + (TPP - 1)] = 1;
    }
}

// ---------------- W split ----------------------------------------------------------
union BV8 { __nv_bfloat16 h[8]; uint4 u; };

__device__ __forceinline__ void split8(const float* v, uint4* ua, uint4* ub)
{
    BV8 a, b;
#pragma unroll
    for (int j = 0; j < 8; j++) {
        __nv_bfloat16 h = __float2bfloat16(v[j]);
        a.h[j] = h;
        b.h[j] = __float2bfloat16(v[j] - __bfloat162float(h));
    }
    *ua = a.u; *ub = b.u;
}

struct SplitW {
    const float* w[3];
    __nv_bfloat16 *wa[3], *wb[3];
};

__global__ void wsplit_all(SplitW S)
{
    int lvl = blockIdx.y;
    int nE  = (128 << lvl) * (128 << lvl);
    int i   = (blockIdx.x * 256 + threadIdx.x) * 8;
    if (i < nE) {
        float v[8];
        *(float4*)&v[0] = *(const float4*)(S.w[lvl] + i);
        *(float4*)&v[4] = *(const float4*)(S.w[lvl] + i + 4);
        split8(v, (uint4*)(S.wa[lvl] + i), (uint4*)(S.wb[lvl] + i));
    }
}

// ---------------- mma.sync bf16 helpers -------------------------------------------
__device__ __forceinline__ uint32_t smem_u32(const void* p)
{
    uint32_t a;
    asm("{ .reg .u64 t; cvta.to.shared.u64 t, %1; cvt.u32.u64 %0, t; }" : "=r"(a) : "l"(p));
    return a;
}

__device__ __forceinline__ void ldm_x4(uint32_t* r, uint32_t addr)
{
    asm volatile("ldmatrix.sync.aligned.m8n8.x4.shared.b16 {%0,%1,%2,%3}, [%4];"
                 : "=r"(r[0]), "=r"(r[1]), "=r"(r[2]), "=r"(r[3]) : "r"(addr));
}

__device__ __forceinline__ void ldm_x4t(uint32_t* r, uint32_t addr)
{
    asm volatile("ldmatrix.sync.aligned.m8n8.x4.trans.shared.b16 {%0,%1,%2,%3}, [%4];"
                 : "=r"(r[0]), "=r"(r[1]), "=r"(r[2]), "=r"(r[3]) : "r"(addr));
}

__device__ __forceinline__ void mma16(float* c, const uint32_t* a, const uint32_t* b)
{
    asm volatile(
        "mma.sync.aligned.m16n8k16.row.col.f32.bf16.bf16.f32 "
        "{%0,%1,%2,%3}, {%4,%5,%6,%7}, {%8,%9}, {%0,%1,%2,%3};"
        : "+f"(c[0]), "+f"(c[1]), "+f"(c[2]), "+f"(c[3])
        : "r"(a[0]), "r"(a[1]), "r"(a[2]), "r"(a[3]), "r"(b[0]), "r"(b[1]));
}

__device__ __forceinline__ void cpa16(uint32_t dst, const void* src)
{
    asm volatile("cp.async.cg.shared.global [%0], [%1], 16;" :: "r"(dst), "l"(src));
}

__device__ __forceinline__ float silu(float y) { return y / (1.0f + expf(-y)); }

// ---------------- conv (R12, banked) ----------------------------------------------
#define BUFSZ 49152

struct ConvTC {
    const __nv_bfloat16 *wa[3], *wb[3];
    const float *x[3];
    const float *gg[3], *bb[3], *mm[3], *vv[3];
    float *pf[3];
};

__global__ void __launch_bounds__(256, 2) conv_bf16_kernel(ConvTC P)
{
    int n = blockIdx.z;
    if (!g_needed[n]) return;

    int bx = blockIdx.x, lvl, p0, d0;
    if (bx < 50)      { lvl = 0; p0 = bx * 128; d0 = 0; }
    else if (bx < 76) { int r = bx - 50; lvl = 1; p0 = (r % 13) * 128; d0 = (r / 13) * 128; }
    else              { int r = bx - 76; lvl = 2; p0 = (r & 3) * 128;  d0 = (r >> 2) * 128; }
    const int C  = 128 << lvl;
    const int HW = 6400 >> (2 * lvl);
    const int NC = C >> 5;

    extern __shared__ uint32_t dsm[];
    char* smp = (char*)dsm;
    const int tid  = threadIdx.x;
    const int lane = tid & 31;
    const int wid  = tid >> 5;
    const int m_off = (wid & 1) * 64;
    const int n_off = (wid >> 1) * 32;
    const int g  = lane >> 2;
    const int tg = lane & 3;
    const uint32_t smb = smem_u32(dsm);

    const __nv_bfloat16* wA1 = P.wa[lvl] + (size_t)d0 * C;
    const __nv_bfloat16* wA2 = P.wb[lvl] + (size_t)d0 * C;
    const float*         xf  = P.x[lvl] + (size_t)n * C * HW;

    float acc[4][4][4];
#pragma unroll
    for (int mi = 0; mi < 4; mi++)
#pragma unroll
        for (int ni = 0; ni < 4; ni++)
#pragma unroll
            for (int r = 0; r < 4; r++) acc[mi][ni][r] = 0.f;

    const int ar0 = tid >> 2,          acb0 = tid & 3;
    const int ar1 = (tid + 256) >> 2,  acb1 = (tid + 256) & 3;
    const uint32_t adof0 = ar0 * 64 + ((acb0 ^ ((ar0 >> 1) & 3)) << 4);
    const uint32_t adof1 = ar1 * 64 + ((acb1 ^ ((ar1 >> 1) & 3)) << 4);

    const int r2  = tid >> 3;
    const int cg  = (tid & 7) * 16;
    const int nb0 = (tid & 7) * 2;
    const uint32_t bo0 = r2 * 256 + ((nb0 ^ (r2 & 7)) << 4);
    const uint32_t bo1 = r2 * 256 + (((nb0 + 1) ^ (r2 & 7)) << 4);

#define STAGE(BUF, KC)                                                              \
    do {                                                                            \
        int k0_ = (KC) * 32;                                                        \
        uint32_t bbuf = smb + (BUF) * BUFSZ;                                        \
        cpa16(bbuf + adof0,        wA1 + (size_t)ar0 * C + k0_ + acb0 * 8);         \
        cpa16(bbuf + adof1,        wA1 + (size_t)ar1 * C + k0_ + acb1 * 8);         \
        cpa16(bbuf + 8192 + adof0, wA2 + (size_t)ar0 * C + k0_ + acb0 * 8);         \
        cpa16(bbuf + 8192 + adof1, wA2 + (size_t)ar1 * C + k0_ + acb1 * 8);         \
        _Pragma("unroll")                                                           \
        for (int t = 0; t < 4; t++) {                                               \
            int slot = tid + t * 256;                                               \
            int rr   = slot >> 5;                                                   \
            int c4   = (slot & 31) * 4;                                             \
            if (p0 + c4 < HW)                                                       \
                cpa16(bbuf + 32768 + slot * 16,                                     \
                      xf + (size_t)(k0_ + rr) * HW + p0 + c4);                      \
            else                                                                    \
                *(uint4*)(smp + (BUF) * BUFSZ + 32768 + slot * 16) =                \
                    make_uint4(0, 0, 0, 0);                                         \
        }                                                                           \
        asm volatile("cp.async.commit_group;");                                     \
    } while (0)

    STAGE(0, 0);

    int cur = 0;
    for (int kc = 0; kc < NC; kc++) {
        asm volatile("cp.async.wait_group 0;");
        __syncthreads();

        {
            char* bufp = smp + cur * BUFSZ;
            const float* xs = (const float*)(bufp + 32768) + r2 * 128 + cg;
            float v[16];
            *(float4*)&v[0]  = *(const float4*)(xs + 0);
            *(float4*)&v[4]  = *(const float4*)(xs + 4);
            *(float4*)&v[8]  = *(const float4*)(xs + 8);
            *(float4*)&v[12] = *(const float4*)(xs + 12);
            uint4 h0, l0, h1, l1;
            split8(v,     &h0, &l0);
            split8(v + 8, &h1, &l1);
            *(uint4*)(bufp + 16384 + bo0) = h0;
            *(uint4*)(bufp + 16384 + bo1) = h1;
            *(uint4*)(bufp + 24576 + bo0) = l0;
            *(uint4*)(bufp + 24576 + bo1) = l1;
        }
        __syncthreads();

        if (kc + 1 < NC) STAGE(cur ^ 1, kc + 1);

        uint32_t base = smb + cur * BUFSZ;
#pragma unroll
        for (int ks = 0; ks < 2; ks++) {
            uint32_t bhf[2][4], blf[2][4];
            int brow = ks * 16 + (lane & 15);
            int nbb  = (n_off >> 3) + (lane >> 4);
#pragma unroll
            for (int nip = 0; nip < 2; nip++) {
                uint32_t boff = brow * 256 + (((nbb + nip * 2) ^ (brow & 7)) << 4);
                ldm_x4t(bhf[nip], base + 16384 + boff);
                ldm_x4t(blf[nip], base + 24576 + boff);
            }
#pragma unroll
            for (int mi = 0; mi < 4; mi++) {
                int arow = m_off + mi * 16 + (lane & 15);
                int cb   = ks * 2 + (lane >> 4);
                uint32_t aoff = arow * 64 + ((cb ^ ((arow >> 1) & 3)) << 4);
                uint32_t ah[4], al[4];
                ldm_x4(ah, base + aoff);
                ldm_x4(al, base + 8192 + aoff);
#pragma unroll
                for (int ni = 0; ni < 4; ni++) {
                    const uint32_t* bh = &bhf[ni >> 1][(ni & 1) * 2];
                    const uint32_t* bl = &blf[ni >> 1][(ni & 1) * 2];
                    mma16(acc[mi][ni], ah, bh);
                    mma16(acc[mi][ni], ah, bl);
                    mma16(acc[mi][ni], al, bh);
                }
            }
        }
        cur ^= 1;
    }

    const float* gg  = P.gg[lvl];
    const float* bbp = P.bb[lvl];
    const float* mm  = P.mm[lvl];
    const float* vv  = P.vv[lvl];
    float*       pf  = P.pf[lvl];
#pragma unroll
    for (int mi = 0; mi < 4; mi++) {
        int r0 = d0 + m_off + mi * 16 + g;
        int r1 = r0 + 8;
        float sc0 = gg[r0] * (1.0f / sqrtf(vv[r0] + 1e-5f));
        float bi0 = bbp[r0] - mm[r0] * sc0;
        float sc1 = gg[r1] * (1.0f / sqrtf(vv[r1] + 1e-5f));
        float bi1 = bbp[r1] - mm[r1] * sc1;
        float* op0 = pf + ((size_t)n * C + r0) * HW;
        float* op1 = pf + ((size_t)n * C + r1) * HW;
#pragma unroll
        for (int ni = 0; ni < 4; ni++) {
            int p = p0 + n_off + ni * 8 + 2 * tg;
            if (p < HW) {
                *(float2*)(op0 + p) = make_float2(silu(acc[mi][ni][0] * sc0 + bi0),
                                                  silu(acc[mi][ni][1] * sc0 + bi0));
                *(float2*)(op1 + p) = make_float2(silu(acc[mi][ni][2] * sc1 + bi1),
                                                  silu(acc[mi][ni][3] * sc1 + bi1));
            }
        }
    }
}

// ---------------- corr: merged levels, group-skip guards --------------------------
template<int C, int H, int W, int STEP, int NG, int WINL>
__device__ __forceinline__ void corr_body(
    float* sm, const float* __restrict__ pf, const float* __restrict__ mlpw,
    float* __restrict__ out, int out_off, int c, int b)
{
    constexpr int PAD = RAD * STEP;
    constexpr int W2  = W + 2 * PAD;
    constexpr int H2  = H + 2 * PAD;
    constexpr int HW  = H * W;
    constexpr int NT  = 256;
    constexpr int NW  = 8;

    float* f1p  = sm;
    float* wred = sm + H2 * W2;

    const int n1   = b * TPP + (TPP - 1);
    const int n2a  = g_idx[b * TFF + 0];
    const int n2b  = g_idx[b * TFF + 1];
    const int tid  = threadIdx.x;
    const int wid  = tid >> 5;
    const int lane = tid & 31;
    // last group real only if its pixel base is in range (skip = bit-identical,
    // since skipped FFMAs multiplied by exact 0)
    const bool hasLast = (NG == 1) || (((tid + NT * (NG - 1)) * 4) < HW);

    const float* f1g = pf + ((size_t)n1  * C + c) * HW;
    const float* f2a = pf + ((size_t)n2a * C + c) * HW;
    const float* f2b = pf + ((size_t)n2b * C + c) * HW;

    for (int q = tid; q < H2 * W2; q += NT) {
        int hh = q / W2 - PAD;
        int ww = q % W2 - PAD;
        float v = 0.f;
        if ((unsigned)hh < (unsigned)H && (unsigned)ww < (unsigned)W)
            v = f1g[hh * W + ww];
        f1p[q] = v;
    }

    float fra[NG][4], frb[NG][4];
    int   basek[NG];
#pragma unroll
    for (int gi = 0; gi < NG; gi++) {
        int p = (tid + NT * gi) * 4;
        if (p < HW) {
            float4 va = *(const float4*)(f2a + p);
            float4 vb = *(const float4*)(f2b + p);
            fra[gi][0] = va.x; fra[gi][1] = va.y; fra[gi][2] = va.z; fra[gi][3] = va.w;
            frb[gi][0] = vb.x; frb[gi][1] = vb.y; frb[gi][2] = vb.z; frb[gi][3] = vb.w;
            basek[gi] = (p / W + PAD) * W2 + (p % W) + PAD;
        } else {
#pragma unroll
            for (int v = 0; v < 4; v++) { fra[gi][v] = 0.f; frb[gi][v] = 0.f; }
            basek[gi] = PAD * W2 + PAD;
        }
    }
    __syncthreads();

    if (WINL == 0) {
        for (int oy = 0; oy < 9; oy++) {
            int ro[NG];
            int dyo = (oy - RAD) * STEP * W2;
#pragma unroll
            for (int gi = 0; gi < NG; gi++) ro[gi] = basek[gi] + dyo;
#pragma unroll
            for (int ox = 0; ox < 9; ox++) {
                const int dxo = (ox - RAD) * STEP;
                float a0 = 0.f, a1 = 0.f, b0 = 0.f, b1 = 0.f;
#pragma unroll
                for (int gi = 0; gi < NG; gi++) {
                    if (gi + 1 == NG && !hasLast) continue;
                    float4 fv = *(const float4*)&f1p[ro[gi] + dxo];
                    a0 = fmaf(fv.x, fra[gi][0], a0);
                    a1 = fmaf(fv.y, fra[gi][1], a1);
                    a0 = fmaf(fv.z, fra[gi][2], a0);
                    a1 = fmaf(fv.w, fra[gi][3], a1);
                    b0 = fmaf(fv.x, frb[gi][0], b0);
                    b1 = fmaf(fv.y, frb[gi][1], b1);
                    b0 = fmaf(fv.z, frb[gi][2], b0);
                    b1 = fmaf(fv.w, frb[gi][3], b1);
                }
                float va = a0 + a1, vb = b0 + b1;
#pragma unroll
                for (int o = 16; o; o >>= 1) {
                    va += __shfl_xor_sync(0xffffffffu, va, o);
                    vb += __shfl_xor_sync(0xffffffffu, vb, o);
                }
                if (lane == 0) {
                    wred[(0 * NW + wid) * NS + oy * 9 + ox] = va;
                    wred[(1 * NW + wid) * NS + oy * 9 + ox] = vb;
                }
            }
        }
    } else {
        for (int oy = 0; oy < 9; oy++) {
            int dyo = (oy - RAD) * STEP * W2;
            float aA[9], aB[9];
#pragma unroll
            for (int ox = 0; ox < 9; ox++) { aA[ox] = 0.f; aB[ox] = 0.f; }
#pragma unroll
            for (int gi = 0; gi < NG; gi++) {
                if (gi + 1 == NG && !hasLast && NG > 1) continue;
                const float* wp = &f1p[basek[gi] + dyo - 4 * STEP];
                float win[WINL > 0 ? WINL : 1];
#pragma unroll
                for (int t = 0; t < WINL / 4; t++) {
                    float4 v = *(const float4*)(wp + 4 * t);
                    win[4 * t] = v.x; win[4 * t + 1] = v.y;
                    win[4 * t + 2] = v.z; win[4 * t + 3] = v.w;
                }
#pragma unroll
                for (int ox = 0; ox < 9; ox++) {
#pragma unroll
                    for (int j = 0; j < 4; j++) {
                        aA[ox] = fmaf(win[STEP * ox + j], fra[gi][j], aA[ox]);
                        aB[ox] = fmaf(win[STEP * ox + j], frb[gi][j], aB[ox]);
                    }
                }
            }
#pragma unroll
            for (int ox = 0; ox < 9; ox++) {
                float va = aA[ox], vb = aB[ox];
#pragma unroll
                for (int o = 16; o; o >>= 1) {
                    va += __shfl_xor_sync(0xffffffffu, va, o);
                    vb += __shfl_xor_sync(0xffffffffu, vb, o);
                }
                if (lane == 0) {
                    wred[(0 * NW + wid) * NS + oy * 9 + ox] = va;
                    wred[(1 * NW + wid) * NS + oy * 9 + ox] = vb;
                }
            }
        }
    }
    __syncthreads();

    if (tid < 64) {
        int q = tid >> 5, l = tid & 31;
        const float* wr = wred + q * NW * NS;
        float v0, v1 = -1e30f, v2 = -1e30f;
        {
            float s0 = 0.f, s1 = 0.f, s2 = 0.f;
#pragma unroll
            for (int w = 0; w < NW; w++) {
                s0 += wr[w * NS + l];
                if (l + 32 < NS) s1 += wr[w * NS + l + 32];
                if (l + 64 < NS) s2 += wr[w * NS + l + 64];
            }
            v0 = s0;
            if (l + 32 < NS) v1 = s1;
            if (l + 64 < NS) v2 = s2;
        }
        float mx = fmaxf(v0, fmaxf(v1, v2));
#pragma unroll
        for (int o = 16; o; o >>= 1)
            mx = fmaxf(mx, __shfl_xor_sync(0xffffffffu, mx, o));
        float e0 = expf(v0 - mx);
        float e1 = (l + 32 < NS) ? expf(v1 - mx) : 0.f;
        float e2 = (l + 64 < NS) ? expf(v2 - mx) : 0.f;
        float w0 = mlpw[l];
        float w1 = (l + 32 < NS) ? mlpw[l + 32] : 0.f;
        float w2 = (l + 64 < NS) ? mlpw[l + 64] : 0.f;
        float ssum = e0 + e1 + e2;
        float dot  = e0 * w0 + e1 * w1 + e2 * w2;
#pragma unroll
        for (int o = 16; o; o >>= 1) {
            ssum += __shfl_xor_sync(0xffffffffu, ssum, o);
            dot  += __shfl_xor_sync(0xffffffffu, dot,  o);
        }
        if (l == 0)
            out[out_off + (b * TFF + q) * C + c] = dot / ssum;
    }
}

__global__ void __launch_bounds__(256, 3) corr_all(
    const float* __restrict__ pf0, const float* __restrict__ pf1,
    const float* __restrict__ pf2, const float* __restrict__ mlpw,
    float* __restrict__ out)
{
    extern __shared__ float smf[];
    int i = blockIdx.x;
    if (i < 512) {
        corr_body<128, 80, 80, 4, 7,  0>(smf, pf0, mlpw, out, 0,    i >> 2, i & 3);
    } else if (i < 1536) {
        int j = i - 512;
        corr_body<256, 40, 40, 2, 2, 20>(smf, pf1, mlpw, out, 1024, j >> 2, j & 3);
    } else {
        int j = i - 1536;
        corr_body<512, 20, 20, 1, 1, 12>(smf, pf2, mlpw, out, 3072, j >> 2, j & 3);
    }
}

// ---------------- launch ----------------------------------------------------------
extern "C" void kernel_launch(void* const* d_in, const int* in_sizes, int n_in,
                              void* d_out, int out_size)
{
    int map_sig [21] = {0,1,2, 3,4,5,6,7, 8,9,10,11,12, 13,14,15,16,17, 18,19,20};
    int map_dict[21] = {0,6,12, 1,2,3,4,5, 7,8,9,10,11, 13,14,15,16,17, 18,19,20};
    const int* map = (in_sizes[1] == 16384) ? map_dict : map_sig;

    const float* mlpw = (const float*)d_in[map[18]];
    const int*   pci  = (const int*)d_in[map[19]];
    const int*   fci  = (const int*)d_in[map[20]];
    float* out = (float*)d_out;

    void* pv;
    cudaGetSymbolAddress(&pv, g_pf0);  float* pf0 = (float*)pv;
    cudaGetSymbolAddress(&pv, g_pf1);  float* pf1 = (float*)pv;
    cudaGetSymbolAddress(&pv, g_pf2);  float* pf2 = (float*)pv;
    __nv_bfloat16 *w0a, *w0b, *w1a, *w1b, *w2a, *w2b;
    cudaGetSymbolAddress(&pv, g_w0a); w0a = (__nv_bfloat16*)pv;
    cudaGetSymbolAddress(&pv, g_w0b); w0b = (__nv_bfloat16*)pv;
    cudaGetSymbolAddress(&pv, g_w1a); w1a = (__nv_bfloat16*)pv;
    cudaGetSymbolAddress(&pv, g_w1b); w1b = (__nv_bfloat16*)pv;
    cudaGetSymbolAddress(&pv, g_w2a); w2a = (__nv_bfloat16*)pv;
    cudaGetSymbolAddress(&pv, g_w2b); w2b = (__nv_bfloat16*)pv;

    prep_kernel<<<1, 1>>>(pci, fci);

    SplitW SW;
    SW.w[0] = (const float*)d_in[map[3]];
    SW.w[1] = (const float*)d_in[map[8]];
    SW.w[2] = (const float*)d_in[map[13]];
    SW.wa[0] = w0a; SW.wa[1] = w1a; SW.wa[2] = w2a;
    SW.wb[0] = w0b; SW.wb[1] = w1b; SW.wb[2] = w2b;
    wsplit_all<<<dim3(128, 3), 256>>>(SW);

    ConvTC P;
    P.wa[0] = w0a; P.wa[1] = w1a; P.wa[2] = w2a;
    P.wb[0] = w0b; P.wb[1] = w1b; P.wb[2] = w2b;
    P.x[0] = (const float*)d_in[map[0]];
    P.x[1] = (const float*)d_in[map[1]];
    P.x[2] = (const float*)d_in[map[2]];
    P.gg[0] = (const float*)d_in[map[4]];  P.gg[1] = (const float*)d_in[map[9]];   P.gg[2] = (const float*)d_in[map[14]];
    P.bb[0] = (const float*)d_in[map[5]];  P.bb[1] = (const float*)d_in[map[10]];  P.bb[2] = (const float*)d_in[map[15]];
    P.mm[0] = (const float*)d_in[map[6]];  P.mm[1] = (const float*)d_in[map[11]];  P.mm[2] = (const float*)d_in[map[16]];
    P.vv[0] = (const float*)d_in[map[7]];  P.vv[1] = (const float*)d_in[map[12]];  P.vv[2] = (const float*)d_in[map[17]];
    P.pf[0] = pf0; P.pf[1] = pf1; P.pf[2] = pf2;

    cudaFuncSetAttribute(conv_bf16_kernel,
                         cudaFuncAttributeMaxDynamicSharedMemorySize, 2 * BUFSZ);
    conv_bf16_kernel<<<dim3(92, 1, NFR), 256, 2 * BUFSZ>>>(P);

    size_t smc = (size_t)(112 * 112 + 2 * 8 * NS) * sizeof(float);
    cudaFuncSetAttribute(corr_all,
                         cudaFuncAttributeMaxDynamicSharedMemorySize, 65536);
    corr_all<<<3584, 256, smc>>>(pf0, pf1, pf2, mlpw, out);
}

// round 17
// speedup vs baseline: 1.4377x; 1.0071x over previous
#include <cuda_runtime.h>
#include <cuda_bf16.h>
#include <math.h>
#include <stdint.h>

#define BB    4
#define TPP   4
#define TFF   2
#define NPAIR (BB*TFF)
#define RAD   4
#define NS    81
#define NFR   (BB*TPP)

// ---------------- scratch ---------------------------------------------------------
__device__ int   g_idx[NPAIR];
__device__ int   g_needed[NFR];
__device__ float g_pf0[(size_t)NFR * 128 * 6400];
__device__ float g_pf1[(size_t)NFR * 256 * 1600];
__device__ float g_pf2[(size_t)NFR * 512 * 400];
__device__ __nv_bfloat16 g_w0a[128*128],  g_w0b[128*128];
__device__ __nv_bfloat16 g_w1a[256*256],  g_w1b[256*256];
__device__ __nv_bfloat16 g_w2a[512*512],  g_w2b[512*512];

// ---------------- prep ------------------------------------------------------------
__global__ void prep_kernel(const int* __restrict__ pci, const int* __restrict__ fci)
{
    if (threadIdx.x != 0 || blockIdx.x != 0) return;
    for (int n = 0; n < NFR; n++) g_needed[n] = 0;
    for (int i = 0; i < BB; i++) {
        int p_pos = TPP - 2;
        for (int j = 0; j < TFF; j++) {
            int f_i = fci[i * TFF + j];
            while (p_pos >= 0) {
                if (p_pos == 0 || f_i < -pci[i * TPP + p_pos - 1]) {
                    int id = p_pos + i * TPP;
                    g_idx[i * TFF + j] = id;
                    g_needed[id] = 1;
                    break;
                }
                p_pos--;
            }
        }
        g_needed[i * TPP + (TPP - 1)] = 1;
    }
}

// ---------------- W split ----------------------------------------------------------
union BV8 { __nv_bfloat16 h[8]; uint4 u; };

__device__ __forceinline__ void split8(const float* v, uint4* ua, uint4* ub)
{
    BV8 a, b;
#pragma unroll
    for (int j = 0; j < 8; j++) {
        __nv_bfloat16 h = __float2bfloat16(v[j]);
        a.h[j] = h;
        b.h[j] = __float2bfloat16(v[j] - __bfloat162float(h));
    }
    *ua = a.u; *ub = b.u;
}

struct SplitW {
    const float* w[3];
    __nv_bfloat16 *wa[3], *wb[3];
};

__global__ void wsplit_all(SplitW S)
{
    int lvl = blockIdx.y;
    int nE  = (128 << lvl) * (128 << lvl);
    int i   = (blockIdx.x * 256 + threadIdx.x) * 8;
    if (i < nE) {
        float v[8];
        *(float4*)&v[0] = *(const float4*)(S.w[lvl] + i);
        *(float4*)&v[4] = *(const float4*)(S.w[lvl] + i + 4);
        split8(v, (uint4*)(S.wa[lvl] + i), (uint4*)(S.wb[lvl] + i));
    }
}

// ---------------- mma.sync bf16 helpers -------------------------------------------
__device__ __forceinline__ uint32_t smem_u32(const void* p)
{
    uint32_t a;
    asm("{ .reg .u64 t; cvta.to.shared.u64 t, %1; cvt.u32.u64 %0, t; }" : "=r"(a) : "l"(p));
    return a;
}

__device__ __forceinline__ void ldm_x4(uint32_t* r, uint32_t addr)
{
    asm volatile("ldmatrix.sync.aligned.m8n8.x4.shared.b16 {%0,%1,%2,%3}, [%4];"
                 : "=r"(r[0]), "=r"(r[1]), "=r"(r[2]), "=r"(r[3]) : "r"(addr));
}

__device__ __forceinline__ void ldm_x4t(uint32_t* r, uint32_t addr)
{
    asm volatile("ldmatrix.sync.aligned.m8n8.x4.trans.shared.b16 {%0,%1,%2,%3}, [%4];"
                 : "=r"(r[0]), "=r"(r[1]), "=r"(r[2]), "=r"(r[3]) : "r"(addr));
}

__device__ __forceinline__ void mma16(float* c, const uint32_t* a, const uint32_t* b)
{
    asm volatile(
        "mma.sync.aligned.m16n8k16.row.col.f32.bf16.bf16.f32 "
        "{%0,%1,%2,%3}, {%4,%5,%6,%7}, {%8,%9}, {%0,%1,%2,%3};"
        : "+f"(c[0]), "+f"(c[1]), "+f"(c[2]), "+f"(c[3])
        : "r"(a[0]), "r"(a[1]), "r"(a[2]), "r"(a[3]), "r"(b[0]), "r"(b[1]));
}

__device__ __forceinline__ void cpa16(uint32_t dst, const void* src)
{
    asm volatile("cp.async.cg.shared.global [%0], [%1], 16;" :: "r"(dst), "l"(src));
}

__device__ __forceinline__ float silu(float y) { return y / (1.0f + __expf(-y)); }

// ---------------- conv (R12, banked) ----------------------------------------------
#define BUFSZ 49152

struct ConvTC {
    const __nv_bfloat16 *wa[3], *wb[3];
    const float *x[3];
    const float *gg[3], *bb[3], *mm[3], *vv[3];
    float *pf[3];
};

__global__ void __launch_bounds__(256, 2) conv_bf16_kernel(ConvTC P)
{
    int n = blockIdx.z;
    if (!g_needed[n]) return;

    int bx = blockIdx.x, lvl, p0, d0;
    if (bx < 50)      { lvl = 0; p0 = bx * 128; d0 = 0; }
    else if (bx < 76) { int r = bx - 50; lvl = 1; p0 = (r % 13) * 128; d0 = (r / 13) * 128; }
    else              { int r = bx - 76; lvl = 2; p0 = (r & 3) * 128;  d0 = (r >> 2) * 128; }
    const int C  = 128 << lvl;
    const int HW = 6400 >> (2 * lvl);
    const int NC = C >> 5;

    extern __shared__ uint32_t dsm[];
    char* smp = (char*)dsm;
    const int tid  = threadIdx.x;
    const int lane = tid & 31;
    const int wid  = tid >> 5;
    const int m_off = (wid & 1) * 64;
    const int n_off = (wid >> 1) * 32;
    const int g  = lane >> 2;
    const int tg = lane & 3;
    const uint32_t smb = smem_u32(dsm);

    const __nv_bfloat16* wA1 = P.wa[lvl] + (size_t)d0 * C;
    const __nv_bfloat16* wA2 = P.wb[lvl] + (size_t)d0 * C;
    const float*         xf  = P.x[lvl] + (size_t)n * C * HW;

    float acc[4][4][4];
#pragma unroll
    for (int mi = 0; mi < 4; mi++)
#pragma unroll
        for (int ni = 0; ni < 4; ni++)
#pragma unroll
            for (int r = 0; r < 4; r++) acc[mi][ni][r] = 0.f;

    const int ar0 = tid >> 2,          acb0 = tid & 3;
    const int ar1 = (tid + 256) >> 2,  acb1 = (tid + 256) & 3;
    const uint32_t adof0 = ar0 * 64 + ((acb0 ^ ((ar0 >> 1) & 3)) << 4);
    const uint32_t adof1 = ar1 * 64 + ((acb1 ^ ((ar1 >> 1) & 3)) << 4);

    const int r2  = tid >> 3;
    const int cg  = (tid & 7) * 16;
    const int nb0 = (tid & 7) * 2;
    const uint32_t bo0 = r2 * 256 + ((nb0 ^ (r2 & 7)) << 4);
    const uint32_t bo1 = r2 * 256 + (((nb0 + 1) ^ (r2 & 7)) << 4);

#define STAGE(BUF, KC)                                                              \
    do {                                                                            \
        int k0_ = (KC) * 32;                                                        \
        uint32_t bbuf = smb + (BUF) * BUFSZ;                                        \
        cpa16(bbuf + adof0,        wA1 + (size_t)ar0 * C + k0_ + acb0 * 8);         \
        cpa16(bbuf + adof1,        wA1 + (size_t)ar1 * C + k0_ + acb1 * 8);         \
        cpa16(bbuf + 8192 + adof0, wA2 + (size_t)ar0 * C + k0_ + acb0 * 8);         \
        cpa16(bbuf + 8192 + adof1, wA2 + (size_t)ar1 * C + k0_ + acb1 * 8);         \
        _Pragma("unroll")                                                           \
        for (int t = 0; t < 4; t++) {                                               \
            int slot = tid + t * 256;                                               \
            int rr   = slot >> 5;                                                   \
            int c4   = (slot & 31) * 4;                                             \
            if (p0 + c4 < HW)                                                       \
                cpa16(bbuf + 32768 + slot * 16,                                     \
                      xf + (size_t)(k0_ + rr) * HW + p0 + c4);                      \
            else                                                                    \
                *(uint4*)(smp + (BUF) * BUFSZ + 32768 + slot * 16) =                \
                    make_uint4(0, 0, 0, 0);                                         \
        }                                                                           \
        asm volatile("cp.async.commit_group;");                                     \
    } while (0)

    STAGE(0, 0);

    int cur = 0;
    for (int kc = 0; kc < NC; kc++) {
        asm volatile("cp.async.wait_group 0;");
        __syncthreads();

        {
            char* bufp = smp + cur * BUFSZ;
            const float* xs = (const float*)(bufp + 32768) + r2 * 128 + cg;
            float v[16];
            *(float4*)&v[0]  = *(const float4*)(xs + 0);
            *(float4*)&v[4]  = *(const float4*)(xs + 4);
            *(float4*)&v[8]  = *(const float4*)(xs + 8);
            *(float4*)&v[12] = *(const float4*)(xs + 12);
            uint4 h0, l0, h1, l1;
            split8(v,     &h0, &l0);
            split8(v + 8, &h1, &l1);
            *(uint4*)(bufp + 16384 + bo0) = h0;
            *(uint4*)(bufp + 16384 + bo1) = h1;
            *(uint4*)(bufp + 24576 + bo0) = l0;
            *(uint4*)(bufp + 24576 + bo1) = l1;
        }
        __syncthreads();

        if (kc + 1 < NC) STAGE(cur ^ 1, kc + 1);

        uint32_t base = smb + cur * BUFSZ;
#pragma unroll
        for (int ks = 0; ks < 2; ks++) {
            uint32_t bhf[2][4], blf[2][4];
            int brow = ks * 16 + (lane & 15);
            int nbb  = (n_off >> 3) + (lane >> 4);
#pragma unroll
            for (int nip = 0; nip < 2; nip++) {
                uint32_t boff = brow * 256 + (((nbb + nip * 2) ^ (brow & 7)) << 4);
                ldm_x4t(bhf[nip], base + 16384 + boff);
                ldm_x4t(blf[nip], base + 24576 + boff);
            }
#pragma unroll
            for (int mi = 0; mi < 4; mi++) {
                int arow = m_off + mi * 16 + (lane & 15);
                int cb   = ks * 2 + (lane >> 4);
                uint32_t aoff = arow * 64 + ((cb ^ ((arow >> 1) & 3)) << 4);
                uint32_t ah[4], al[4];
                ldm_x4(ah, base + aoff);
                ldm_x4(al, base + 8192 + aoff);
#pragma unroll
                for (int ni = 0; ni < 4; ni++) {
                    const uint32_t* bh = &bhf[ni >> 1][(ni & 1) * 2];
                    const uint32_t* bl = &blf[ni >> 1][(ni & 1) * 2];
                    mma16(acc[mi][ni], ah, bh);
                    mma16(acc[mi][ni], ah, bl);
                    mma16(acc[mi][ni], al, bh);
                }
            }
        }
        cur ^= 1;
    }

    const float* gg  = P.gg[lvl];
    const float* bbp = P.bb[lvl];
    const float* mm  = P.mm[lvl];
    const float* vv  = P.vv[lvl];
    float*       pf  = P.pf[lvl];
#pragma unroll
    for (int mi = 0; mi < 4; mi++) {
        int r0 = d0 + m_off + mi * 16 + g;
        int r1 = r0 + 8;
        float sc0 = gg[r0] * (1.0f / sqrtf(vv[r0] + 1e-5f));
        float bi0 = bbp[r0] - mm[r0] * sc0;
        float sc1 = gg[r1] * (1.0f / sqrtf(vv[r1] + 1e-5f));
        float bi1 = bbp[r1] - mm[r1] * sc1;
        float* op0 = pf + ((size_t)n * C + r0) * HW;
        float* op1 = pf + ((size_t)n * C + r1) * HW;
#pragma unroll
        for (int ni = 0; ni < 4; ni++) {
            int p = p0 + n_off + ni * 8 + 2 * tg;
            if (p < HW) {
                *(float2*)(op0 + p) = make_float2(silu(acc[mi][ni][0] * sc0 + bi0),
                                                  silu(acc[mi][ni][1] * sc0 + bi0));
                *(float2*)(op1 + p) = make_float2(silu(acc[mi][ni][2] * sc1 + bi1),
                                                  silu(acc[mi][ni][3] * sc1 + bi1));
            }
        }
    }
}

// ---------------- corr: merged levels, group-skip guards --------------------------
template<int C, int H, int W, int STEP, int NG, int WINL>
__device__ __forceinline__ void corr_body(
    float* sm, const float* __restrict__ pf, const float* __restrict__ mlpw,
    float* __restrict__ out, int out_off, int c, int b)
{
    constexpr int PAD = RAD * STEP;
    constexpr int W2  = W + 2 * PAD;
    constexpr int H2  = H + 2 * PAD;
    constexpr int HW  = H * W;
    constexpr int NT  = 256;
    constexpr int NW  = 8;

    float* f1p  = sm;
    float* wred = sm + H2 * W2;

    const int n1   = b * TPP + (TPP - 1);
    const int n2a  = g_idx[b * TFF + 0];
    const int n2b  = g_idx[b * TFF + 1];
    const int tid  = threadIdx.x;
    const int wid  = tid >> 5;
    const int lane = tid & 31;
    const bool hasLast = (NG == 1) || (((tid + NT * (NG - 1)) * 4) < HW);

    const float* f1g = pf + ((size_t)n1  * C + c) * HW;
    const float* f2a = pf + ((size_t)n2a * C + c) * HW;
    const float* f2b = pf + ((size_t)n2b * C + c) * HW;

    for (int q = tid; q < H2 * W2; q += NT) {
        int hh = q / W2 - PAD;
        int ww = q % W2 - PAD;
        float v = 0.f;
        if ((unsigned)hh < (unsigned)H && (unsigned)ww < (unsigned)W)
            v = f1g[hh * W + ww];
        f1p[q] = v;
    }

    float fra[NG][4], frb[NG][4];
    int   basek[NG];
#pragma unroll
    for (int gi = 0; gi < NG; gi++) {
        int p = (tid + NT * gi) * 4;
        if (p < HW) {
            float4 va = *(const float4*)(f2a + p);
            float4 vb = *(const float4*)(f2b + p);
            fra[gi][0] = va.x; fra[gi][1] = va.y; fra[gi][2] = va.z; fra[gi][3] = va.w;
            frb[gi][0] = vb.x; frb[gi][1] = vb.y; frb[gi][2] = vb.z; frb[gi][3] = vb.w;
            basek[gi] = (p / W + PAD) * W2 + (p % W) + PAD;
        } else {
#pragma unroll
            for (int v = 0; v < 4; v++) { fra[gi][v] = 0.f; frb[gi][v] = 0.f; }
            basek[gi] = PAD * W2 + PAD;
        }
    }
    __syncthreads();

    if (WINL == 0) {
        for (int oy = 0; oy < 9; oy++) {
            int ro[NG];
            int dyo = (oy - RAD) * STEP * W2;
#pragma unroll
            for (int gi = 0; gi < NG; gi++) ro[gi] = basek[gi] + dyo;
#pragma unroll
            for (int ox = 0; ox < 9; ox++) {
                const int dxo = (ox - RAD) * STEP;
                float a0 = 0.f, a1 = 0.f, b0 = 0.f, b1 = 0.f;
#pragma unroll
                for (int gi = 0; gi < NG; gi++) {
                    if (gi + 1 == NG && !hasLast) continue;
                    float4 fv = *(const float4*)&f1p[ro[gi] + dxo];
                    a0 = fmaf(fv.x, fra[gi][0], a0);
                    a1 = fmaf(fv.y, fra[gi][1], a1);
                    a0 = fmaf(fv.z, fra[gi][2], a0);
                    a1 = fmaf(fv.w, fra[gi][3], a1);
                    b0 = fmaf(fv.x, frb[gi][0], b0);
                    b1 = fmaf(fv.y, frb[gi][1], b1);
                    b0 = fmaf(fv.z, frb[gi][2], b0);
                    b1 = fmaf(fv.w, frb[gi][3], b1);
                }
                float va = a0 + a1, vb = b0 + b1;
#pragma unroll
                for (int o = 16; o; o >>= 1) {
                    va += __shfl_xor_sync(0xffffffffu, va, o);
                    vb += __shfl_xor_sync(0xffffffffu, vb, o);
                }
                if (lane == 0) {
                    wred[(0 * NW + wid) * NS + oy * 9 + ox] = va;
                    wred[(1 * NW + wid) * NS + oy * 9 + ox] = vb;
                }
            }
        }
    } else {
        for (int oy = 0; oy < 9; oy++) {
            int dyo = (oy - RAD) * STEP * W2;
            float aA[9], aB[9];
#pragma unroll
            for (int ox = 0; ox < 9; ox++) { aA[ox] = 0.f; aB[ox] = 0.f; }
#pragma unroll
            for (int gi = 0; gi < NG; gi++) {
                if (gi + 1 == NG && !hasLast && NG > 1) continue;
                const float* wp = &f1p[basek[gi] + dyo - 4 * STEP];
                float win[WINL > 0 ? WINL : 1];
#pragma unroll
                for (int t = 0; t < WINL / 4; t++) {
                    float4 v = *(const float4*)(wp + 4 * t);
                    win[4 * t] = v.x; win[4 * t + 1] = v.y;
                    win[4 * t + 2] = v.z; win[4 * t + 3] = v.w;
                }
#pragma unroll
                for (int ox = 0; ox < 9; ox++) {
#pragma unroll
                    for (int j = 0; j < 4; j++) {
                        aA[ox] = fmaf(win[STEP * ox + j], fra[gi][j], aA[ox]);
                        aB[ox] = fmaf(win[STEP * ox + j], frb[gi][j], aB[ox]);
                    }
                }
            }
#pragma unroll
            for (int ox = 0; ox < 9; ox++) {
                float va = aA[ox], vb = aB[ox];
#pragma unroll
                for (int o = 16; o; o >>= 1) {
                    va += __shfl_xor_sync(0xffffffffu, va, o);
                    vb += __shfl_xor_sync(0xffffffffu, vb, o);
                }
                if (lane == 0) {
                    wred[(0 * NW + wid) * NS + oy * 9 + ox] = va;
                    wred[(1 * NW + wid) * NS + oy * 9 + ox] = vb;
                }
            }
        }
    }
    __syncthreads();

    if (tid < 64) {
        int q = tid >> 5, l = tid & 31;
        const float* wr = wred + q * NW * NS;
        float v0, v1 = -1e30f, v2 = -1e30f;
        {
            float s0 = 0.f, s1 = 0.f, s2 = 0.f;
#pragma unroll
            for (int w = 0; w < NW; w++) {
                s0 += wr[w * NS + l];
                if (l + 32 < NS) s1 += wr[w * NS + l + 32];
                if (l + 64 < NS) s2 += wr[w * NS + l + 64];
            }
            v0 = s0;
            if (l + 32 < NS) v1 = s1;
            if (l + 64 < NS) v2 = s2;
        }
        float mx = fmaxf(v0, fmaxf(v1, v2));
#pragma unroll
        for (int o = 16; o; o >>= 1)
            mx = fmaxf(mx, __shfl_xor_sync(0xffffffffu, mx, o));
        float e0 = __expf(v0 - mx);
        float e1 = (l + 32 < NS) ? __expf(v1 - mx) : 0.f;
        float e2 = (l + 64 < NS) ? __expf(v2 - mx) : 0.f;
        float w0 = mlpw[l];
        float w1 = (l + 32 < NS) ? mlpw[l + 32] : 0.f;
        float w2 = (l + 64 < NS) ? mlpw[l + 64] : 0.f;
        float ssum = e0 + e1 + e2;
        float dot  = e0 * w0 + e1 * w1 + e2 * w2;
#pragma unroll
        for (int o = 16; o; o >>= 1) {
            ssum += __shfl_xor_sync(0xffffffffu, ssum, o);
            dot  += __shfl_xor_sync(0xffffffffu, dot,  o);
        }
        if (l == 0)
            out[out_off + (b * TFF + q) * C + c] = dot / ssum;
    }
}

__global__ void __launch_bounds__(256, 3) corr_all(
    const float* __restrict__ pf0, const float* __restrict__ pf1,
    const float* __restrict__ pf2, const float* __restrict__ mlpw,
    float* __restrict__ out)
{
    extern __shared__ float smf[];
    int i = blockIdx.x;
    if (i < 512) {
        corr_body<128, 80, 80, 4, 7,  0>(smf, pf0, mlpw, out, 0,    i >> 2, i & 3);
    } else if (i < 1536) {
        int j = i - 512;
        corr_body<256, 40, 40, 2, 2, 20>(smf, pf1, mlpw, out, 1024, j >> 2, j & 3);
    } else {
        int j = i - 1536;
        corr_body<512, 20, 20, 1, 1, 12>(smf, pf2, mlpw, out, 3072, j >> 2, j & 3);
    }
}

// ---------------- launch ----------------------------------------------------------
extern "C" void kernel_launch(void* const* d_in, const int* in_sizes, int n_in,
                              void* d_out, int out_size)
{
    int map_sig [21] = {0,1,2, 3,4,5,6,7, 8,9,10,11,12, 13,14,15,16,17, 18,19,20};
    int map_dict[21] = {0,6,12, 1,2,3,4,5, 7,8,9,10,11, 13,14,15,16,17, 18,19,20};
    const int* map = (in_sizes[1] == 16384) ? map_dict : map_sig;

    const float* mlpw = (const float*)d_in[map[18]];
    const int*   pci  = (const int*)d_in[map[19]];
    const int*   fci  = (const int*)d_in[map[20]];
    float* out = (float*)d_out;

    void* pv;
    cudaGetSymbolAddress(&pv, g_pf0);  float* pf0 = (float*)pv;
    cudaGetSymbolAddress(&pv, g_pf1);  float* pf1 = (float*)pv;
    cudaGetSymbolAddress(&pv, g_pf2);  float* pf2 = (float*)pv;
    __nv_bfloat16 *w0a, *w0b, *w1a, *w1b, *w2a, *w2b;
    cudaGetSymbolAddress(&pv, g_w0a); w0a = (__nv_bfloat16*)pv;
    cudaGetSymbolAddress(&pv, g_w0b); w0b = (__nv_bfloat16*)pv;
    cudaGetSymbolAddress(&pv, g_w1a); w1a = (__nv_bfloat16*)pv;
    cudaGetSymbolAddress(&pv, g_w1b); w1b = (__nv_bfloat16*)pv;
    cudaGetSymbolAddress(&pv, g_w2a); w2a = (__nv_bfloat16*)pv;
    cudaGetSymbolAddress(&pv, g_w2b); w2b = (__nv_bfloat16*)pv;

    prep_kernel<<<1, 1>>>(pci, fci);

    SplitW SW;
    SW.w[0] = (const float*)d_in[map[3]];
    SW.w[1] = (const float*)d_in[map[8]];
    SW.w[2] = (const float*)d_in[map[13]];
    SW.wa[0] = w0a; SW.wa[1] = w1a; SW.wa[2] = w2a;
    SW.wb[0] = w0b; SW.wb[1] = w1b; SW.wb[2] = w2b;
    wsplit_all<<<dim3(128, 3), 256>>>(SW);

    ConvTC P;
    P.wa[0] = w0a; P.wa[1] = w1a; P.wa[2] = w2a;
    P.wb[0] = w0b; P.wb[1] = w1b; P.wb[2] = w2b;
    P.x[0] = (const float*)d_in[map[0]];
    P.x[1] = (const float*)d_in[map[1]];
    P.x[2] = (const float*)d_in[map[2]];
    P.gg[0] = (const float*)d_in[map[4]];  P.gg[1] = (const float*)d_in[map[9]];   P.gg[2] = (const float*)d_in[map[14]];
    P.bb[0] = (const float*)d_in[map[5]];  P.bb[1] = (const float*)d_in[map[10]];  P.bb[2] = (const float*)d_in[map[15]];
    P.mm[0] = (const float*)d_in[map[6]];  P.mm[1] = (const float*)d_in[map[11]];  P.mm[2] = (const float*)d_in[map[16]];
    P.vv[0] = (const float*)d_in[map[7]];  P.vv[1] = (const float*)d_in[map[12]];  P.vv[2] = (const float*)d_in[map[17]];
    P.pf[0] = pf0; P.pf[1] = pf1; P.pf[2] = pf2;

    cudaFuncSetAttribute(conv_bf16_kernel,
                         cudaFuncAttributeMaxDynamicSharedMemorySize, 2 * BUFSZ);
    conv_bf16_kernel<<<dim3(92, 1, NFR), 256, 2 * BUFSZ>>>(P);

    size_t smc = (size_t)(112 * 112 + 2 * 8 * NS) * sizeof(float);
    cudaFuncSetAttribute(corr_all,
                         cudaFuncAttributeMaxDynamicSharedMemorySize, 65536);
    corr_all<<<3584, 256, smc>>>(pf0, pf1, pf2, mlpw, out);
}